// round 1
// baseline (speedup 1.0000x reference)
#include <cuda_runtime.h>

#define BB   4
#define CC   64
#define HWD  4096
#define QKD  8

// ---------------- device scratch (no allocations allowed) ----------------
__device__ float g_Q[BB*QKD*HWD];
__device__ float g_K[BB*QKD*HWD];
__device__ float g_V[BB*CC*HWD];
__device__ float g_f1[BB*64*32*32];
__device__ float g_f2[BB*128];
__device__ int   g_branch[BB];
__device__ float g_sobel[BB*HWD];
__device__ float g_hsv[BB*HWD];
__device__ float g_hist[BB*HWD];
__device__ float g_fftmag[BB*CC*HWD];
__device__ float g_spatial[BB*HWD];

__device__ const int c_branch_tab[25] =
    {0,0,0,0,0,0,1,1,0,0,0,0,0,0,3,1,1,2,3,0,0,3,3,3,3};

__device__ __forceinline__ float sigmoidf_(float z){ return 1.0f/(1.0f+__expf(-z)); }

// ---------------- classifier conv1: x[4,64,64,64] -> relu -> f1[4,64,32,32] ----------------
__global__ void conv1_kernel(const float* __restrict__ x,
                             const float* __restrict__ w,
                             const float* __restrict__ bias){
    const int ocg = blockIdx.x;   // 0..31, 2 output channels each
    const int b   = blockIdx.y;
    const int t   = threadIdx.x;  // 256
    __shared__ float xs[64*64];
    __shared__ float ws[2*64*9];
    for (int i = t; i < 2*64*9; i += 256) ws[i] = w[ocg*2*576 + i];
    float acc[4][2];
    #pragma unroll
    for (int i=0;i<4;i++){ acc[i][0]=0.f; acc[i][1]=0.f; }
    for (int ic = 0; ic < 64; ++ic){
        __syncthreads();
        const float* xp = x + (((size_t)b*64+ic)<<12);
        for (int i = t; i < 4096; i += 256) xs[i] = xp[i];
        __syncthreads();
        #pragma unroll
        for (int i=0;i<4;i++){
            int p  = i*256 + t;
            int oy = p>>5, ox = p&31;
            int iy0 = 2*oy-1, ix0 = 2*ox-1;
            float xv[9];
            #pragma unroll
            for (int ky=0;ky<3;ky++)
                #pragma unroll
                for (int kx=0;kx<3;kx++){
                    int iy=iy0+ky, ix=ix0+kx;
                    xv[ky*3+kx] = (iy>=0&&iy<64&&ix>=0&&ix<64)? xs[(iy<<6)+ix] : 0.0f;
                }
            #pragma unroll
            for (int ol=0;ol<2;ol++){
                const float* wp = ws + ol*576 + ic*9;
                float s = acc[i][ol];
                #pragma unroll
                for (int k=0;k<9;k++) s += xv[k]*wp[k];
                acc[i][ol] = s;
            }
        }
    }
    #pragma unroll
    for (int ol=0;ol<2;ol++){
        int oc = ocg*2+ol;
        float bv = bias[oc];
        #pragma unroll
        for (int i=0;i<4;i++){
            int p = i*256+t;
            float v = acc[i][ol]+bv;
            g_f1[(((b*64)+oc)<<10)+p] = v>0.f? v : 0.f;
        }
    }
}

// ---------------- conv2 + relu + spatial mean: f1 -> f2[4,128] ----------------
__global__ void conv2_kernel(const float* __restrict__ w,
                             const float* __restrict__ bias){
    const int oc = blockIdx.x;   // 0..127
    const int b  = blockIdx.y;
    const int t  = threadIdx.x;  // 256, one output pixel each (16x16)
    __shared__ float xs[32*32];
    __shared__ float ws[64*9];
    __shared__ float red[256];
    for (int i=t;i<576;i+=256) ws[i]=w[oc*576+i];
    int oy=t>>4, ox=t&15;
    int iy0=2*oy-1, ix0=2*ox-1;
    float acc=0.f;
    for (int ic=0;ic<64;++ic){
        __syncthreads();
        const float* xp = g_f1 + (((b*64)+ic)<<10);
        for (int i=t;i<1024;i+=256) xs[i]=xp[i];
        __syncthreads();
        const float* wp = ws + ic*9;
        #pragma unroll
        for (int ky=0;ky<3;ky++)
            #pragma unroll
            for (int kx=0;kx<3;kx++){
                int iy=iy0+ky, ix=ix0+kx;
                float xv = (iy>=0&&iy<32&&ix>=0&&ix<32)? xs[(iy<<5)+ix] : 0.0f;
                acc += xv*wp[ky*3+kx];
            }
    }
    acc += bias[oc];
    acc = acc>0.f? acc : 0.f;
    red[t]=acc; __syncthreads();
    for (int s=128;s>0;s>>=1){ if(t<s) red[t]+=red[t+s]; __syncthreads(); }
    if (t==0) g_f2[b*128+oc] = red[0]*(1.0f/256.0f);
}

// ---------------- fc + argmax -> branch id per sample ----------------
__global__ void fc_argmax_kernel(const float* __restrict__ fcw,
                                 const float* __restrict__ fcb){
    int wid = threadIdx.x>>5, lane = threadIdx.x&31;
    if (wid >= BB) return;
    float v = -1e30f; int idx = lane;
    if (lane < 25){
        float s = fcb[lane];
        const float* f2   = g_f2 + wid*128;
        const float* wrow = fcw  + lane*128;
        #pragma unroll 4
        for (int k=0;k<128;k++) s += f2[k]*wrow[k];
        v = s;
    }
    #pragma unroll
    for (int off=16;off>0;off>>=1){
        float ov = __shfl_down_sync(0xffffffffu, v,   off);
        int   oi = __shfl_down_sync(0xffffffffu, idx, off);
        if (ov > v || (ov==v && oi<idx)){ v=ov; idx=oi; }
    }
    if (lane==0) g_branch[wid] = c_branch_tab[idx];
}

// ---------------- QKV projections (1x1 convs) ----------------
__global__ void qkv_kernel(const float* __restrict__ x,
    const float* __restrict__ wq, const float* __restrict__ bq,
    const float* __restrict__ wk, const float* __restrict__ bk,
    const float* __restrict__ wv, const float* __restrict__ bv){
    __shared__ __align__(16) float wqt[64*8];
    __shared__ __align__(16) float wkt[64*8];
    __shared__ __align__(16) float wvt[64*64];
    const int t = threadIdx.x;   // 128
    for (int i=t;i<512;i+=128){ int o=i>>6,c=i&63; wqt[c*8+o]=wq[i]; wkt[c*8+o]=wk[i]; }
    for (int i=t;i<4096;i+=128){ int o=i>>6,c=i&63; wvt[c*64+o]=wv[i]; }
    __syncthreads();
    const int b = blockIdx.y;
    const int n = blockIdx.x*128 + t;
    float aq[8], ak[8], av[64];
    #pragma unroll
    for (int o=0;o<8;o++){ aq[o]=bq[o]; ak[o]=bk[o]; }
    #pragma unroll
    for (int o=0;o<64;o++) av[o]=bv[o];
    const float* xb = x + (size_t)b*CC*HWD + n;
    float xc = xb[0];
    for (int c=0;c<64;c++){
        float xn = (c<63)? xb[(c+1)*HWD] : 0.0f;  // prefetch next channel
        const float4* wv4 = (const float4*)(wvt + c*64);
        #pragma unroll
        for (int j=0;j<16;j++){
            float4 v = wv4[j];
            av[4*j+0]+=v.x*xc; av[4*j+1]+=v.y*xc; av[4*j+2]+=v.z*xc; av[4*j+3]+=v.w*xc;
        }
        const float4* wq4 = (const float4*)(wqt + c*8);
        const float4* wk4 = (const float4*)(wkt + c*8);
        #pragma unroll
        for (int j=0;j<2;j++){
            float4 q4=wq4[j], k4=wk4[j];
            aq[4*j+0]+=q4.x*xc; aq[4*j+1]+=q4.y*xc; aq[4*j+2]+=q4.z*xc; aq[4*j+3]+=q4.w*xc;
            ak[4*j+0]+=k4.x*xc; ak[4*j+1]+=k4.y*xc; ak[4*j+2]+=k4.z*xc; ak[4*j+3]+=k4.w*xc;
        }
        xc = xn;
    }
    #pragma unroll
    for (int o=0;o<8;o++){
        g_Q[((b<<3)+o)*HWD + n] = aq[o];
        g_K[((b<<3)+o)*HWD + n] = ak[o];
    }
    #pragma unroll
    for (int o=0;o<64;o++) g_V[((b<<6)+o)*HWD + n] = av[o];
}

// ---------------- sobel / hsv / hist maps ----------------
__global__ void spatial3_kernel(const float* __restrict__ x){
    int id = blockIdx.x*128 + threadIdx.x;  // 16384 threads
    int b = id>>12, p = id&4095;
    int y = p>>6, xw = p&63;
    float ssum=0.f, csum=0.f, mx=-1e30f, mn=1e30f;
    const float* xb = x + ((size_t)b<<18);
    for (int c=0;c<64;c++){
        const float* xp = xb + (c<<12);
        float v[3][3];
        #pragma unroll
        for (int dy=-1;dy<=1;dy++)
            #pragma unroll
            for (int dx=-1;dx<=1;dx++){
                int yy=y+dy, xx=xw+dx;
                v[dy+1][dx+1] = (yy>=0&&yy<64&&xx>=0&&xx<64)? xp[(yy<<6)+xx] : 0.0f;
            }
        float gx = (v[0][2]+2.f*v[1][2]+v[2][2]) - (v[0][0]+2.f*v[1][0]+v[2][0]);
        float gy = (v[2][0]+2.f*v[2][1]+v[2][2]) - (v[0][0]+2.f*v[0][1]+v[0][2]);
        ssum += sqrtf(gx*gx+gy*gy);
        float ctr = v[1][1];
        csum += ctr; mx = fmaxf(mx,ctr); mn = fminf(mn,ctr);
    }
    g_sobel[id] = sigmoidf_(ssum*(1.0f/64.0f));
    g_hsv[id]   = (mx-mn+1e-6f)/(mx+1e-6f);
    g_hist[id]  = sigmoidf_(csum*(1.0f/64.0f));
}

// ---------------- 64x64 DFT magnitude (fftshifted) per (b,c) ----------------
__global__ void fft_kernel(const float* __restrict__ x){
    extern __shared__ float sm[];
    float* xs  = sm;            // 4096 real input
    float* re  = sm + 4096;     // 4096 row-FFT real
    float* im  = sm + 8192;     // 4096 row-FFT imag
    float* twc = sm + 12288;    // 64 cos
    float* tws = sm + 12352;    // 64 sin (negative-frequency convention)
    const int c = blockIdx.x, b = blockIdx.y;
    const int t = threadIdx.x;  // 256
    const float* xp = x + ((size_t)(((b<<6)+c))<<12);
    for (int i=t;i<4096;i+=256) xs[i]=xp[i];
    if (t<64){ float s,co; sincosf(-6.283185307179586f * (float)t * (1.0f/64.0f), &s, &co); twc[t]=co; tws[t]=s; }
    __syncthreads();
    // row pass: real -> complex
    for (int o=t;o<4096;o+=256){
        int r=o>>6, v=o&63;
        const float* row = xs + (r<<6);
        float cr=0.f, ci=0.f;
        #pragma unroll 4
        for (int j=0;j<64;j++){
            int ti = (v*j)&63;
            float xv = row[j];
            cr += xv*twc[ti];
            ci += xv*tws[ti];
        }
        re[o]=cr; im[o]=ci;
    }
    __syncthreads();
    // column pass + magnitude + fftshift
    float* outp = g_fftmag + ((size_t)(((b<<6)+c))<<12);
    for (int o=t;o<4096;o+=256){
        int u=o>>6, v=o&63;
        float fr=0.f, fi=0.f;
        #pragma unroll 4
        for (int r=0;r<64;r++){
            int ti=(u*r)&63;
            float a = re[(r<<6)+v], bm = im[(r<<6)+v];
            float tc=twc[ti], ts=tws[ti];
            fr += a*tc - bm*ts;
            fi += a*ts + bm*tc;
        }
        float mag = sqrtf(fr*fr+fi*fi);
        int su=(u+32)&63, sv=(v+32)&63;
        outp[(su<<6)+sv]=mag;
    }
}

// ---------------- select map per sample by branch, scale by spatial_weight ----------------
__global__ void combine_kernel(const float* __restrict__ swp){
    int id = blockIdx.x*256+threadIdx.x;  // 16384
    int b = id>>12, p = id&4095;
    int br = g_branch[b];
    float v;
    if      (br==0) v = g_sobel[id];
    else if (br==1) v = g_hsv[id];
    else if (br==2) v = g_hist[id];
    else {
        float s=0.f;
        const float* mp = g_fftmag + ((size_t)b<<18) + p;
        #pragma unroll 4
        for (int c=0;c<64;c++) s += mp[(size_t)c<<12];
        v = sigmoidf_(s*(1.0f/64.0f));
    }
    g_spatial[id] = swp[0]*v;
}

// ---------------- fused flash attention + routed-spatial epilogue ----------------
__global__ void __launch_bounds__(256) attention_kernel(const float* __restrict__ x,
                                                        float* __restrict__ out){
    __shared__ __align__(16) float Ks[8*128];
    __shared__ __align__(16) float Vs[128*68];   // pad 68 to keep rows 16B-aligned
    const int t    = threadIdx.x;
    const int b    = blockIdx.y;
    const int qi   = t>>1, half = t&1;           // 2 threads per query, 32 channels each
    const int n    = blockIdx.x*128 + qi;
    float qd[8];
    #pragma unroll
    for (int d=0;d<8;d++) qd[d] = g_Q[((b<<3)+d)*HWD + n] * 0.35355339059327373f;
    float acc[32];
    #pragma unroll
    for (int j=0;j<32;j++) acc[j]=0.f;
    float denom=0.f;
    for (int kt=0;kt<32;kt++){
        int m0 = kt<<7;
        for (int i=t;i<1024;i+=256){ int d=i>>7,m=i&127; Ks[i] = g_K[((b<<3)+d)*HWD + m0+m]; }
        for (int i=t;i<8192;i+=256){ int c=i>>7,m=i&127; Vs[m*68+c] = g_V[((b<<6)+c)*HWD + m0+m]; }
        __syncthreads();
        #pragma unroll 2
        for (int m=0;m<128;m++){
            float s = qd[0]*Ks[m];
            #pragma unroll
            for (int d=1;d<8;d++) s += qd[d]*Ks[(d<<7)+m];
            float e = __expf(s);
            denom += e;
            const float4* vr = (const float4*)(Vs + m*68 + (half<<5));
            #pragma unroll
            for (int j=0;j<8;j++){
                float4 v = vr[j];
                acc[4*j+0]+=e*v.x; acc[4*j+1]+=e*v.y; acc[4*j+2]+=e*v.z; acc[4*j+3]+=e*v.w;
            }
        }
        __syncthreads();
    }
    float sp    = g_spatial[(b<<12)+n];
    float scale = sp / denom;
    const float* xb = x  + ((size_t)b<<18) + n;
    float*       ob = out+ ((size_t)b<<18) + n;
    #pragma unroll
    for (int j=0;j<32;j++){
        int cidx = (half<<5)+j;
        ob[(size_t)cidx<<12] = acc[j]*scale + xb[(size_t)cidx<<12];
    }
}

// ---------------- launch ----------------
extern "C" void kernel_launch(void* const* d_in, const int* in_sizes, int n_in,
                              void* d_out, int out_size){
    const float* x    = (const float*)d_in[0];
    const float* wq   = (const float*)d_in[1];
    const float* bq   = (const float*)d_in[2];
    const float* wk   = (const float*)d_in[3];
    const float* bk   = (const float*)d_in[4];
    const float* wv   = (const float*)d_in[5];
    const float* bv   = (const float*)d_in[6];
    const float* c1w  = (const float*)d_in[7];
    const float* c1b  = (const float*)d_in[8];
    const float* c2w  = (const float*)d_in[9];
    const float* c2b  = (const float*)d_in[10];
    const float* fcw  = (const float*)d_in[11];
    const float* fcb  = (const float*)d_in[12];
    const float* swp  = (const float*)d_in[13];
    float* out = (float*)d_out;

    cudaFuncSetAttribute(fft_kernel, cudaFuncAttributeMaxDynamicSharedMemorySize, 49664);

    conv1_kernel   <<<dim3(32,4), 256>>>(x, c1w, c1b);
    conv2_kernel   <<<dim3(128,4),256>>>(c2w, c2b);
    fc_argmax_kernel<<<1,128>>>(fcw, fcb);
    qkv_kernel     <<<dim3(32,4), 128>>>(x, wq,bq, wk,bk, wv,bv);
    spatial3_kernel<<<128,128>>>(x);
    fft_kernel     <<<dim3(64,4), 256, 49664>>>(x);
    combine_kernel <<<64,256>>>(swp);
    attention_kernel<<<dim3(32,4),256>>>(x, out);
}

// round 2
// speedup vs baseline: 1.3252x; 1.3252x over previous
#include <cuda_runtime.h>

#define BB   4
#define CC   64
#define HWD  4096
#define QKD  8

// ---------------- device scratch (no allocations allowed) ----------------
__device__ float g_Q[BB*QKD*HWD];
__device__ float g_K[BB*QKD*HWD];
__device__ float g_V[BB*CC*HWD];
__device__ float g_f1[BB*64*32*32];
__device__ float g_f2[BB*128];
__device__ int   g_branch[BB];
__device__ float g_sobel[BB*HWD];
__device__ float g_hsv[BB*HWD];
__device__ float g_hist[BB*HWD];
__device__ float g_fftmag[BB*CC*HWD];
__device__ float g_spatial[BB*HWD];

__device__ const int c_branch_tab[25] =
    {0,0,0,0,0,0,1,1,0,0,0,0,0,0,3,1,1,2,3,0,0,3,3,3,3};

__device__ __forceinline__ float sigmoidf_(float z){ return 1.0f/(1.0f+__expf(-z)); }

// packed fp32x2 helpers (Blackwell paired-FP32 pipe)
__device__ __forceinline__ void fma2_(unsigned long long& d,
                                      unsigned long long a,
                                      unsigned long long b){
    asm("fma.rn.f32x2 %0, %1, %2, %0;" : "+l"(d) : "l"(a), "l"(b));
}
__device__ __forceinline__ unsigned long long dup2_(float v){
    unsigned long long d; unsigned int u = __float_as_uint(v);
    asm("mov.b64 %0, {%1, %1};" : "=l"(d) : "r"(u));
    return d;
}
__device__ __forceinline__ void unpack2_(unsigned long long v, float& lo, float& hi){
    unsigned int a, b;
    asm("mov.b64 {%0, %1}, %2;" : "=r"(a), "=r"(b) : "l"(v));
    lo = __uint_as_float(a); hi = __uint_as_float(b);
}

// ---------------- classifier conv1: x[4,64,64,64] -> relu -> f1[4,64,32,32] ----------------
__global__ void conv1_kernel(const float* __restrict__ x,
                             const float* __restrict__ w,
                             const float* __restrict__ bias){
    const int ocg = blockIdx.x;   // 0..31, 2 output channels each
    const int b   = blockIdx.y;
    const int t   = threadIdx.x;  // 256
    __shared__ float xs[64*64];
    __shared__ float ws[2*64*9];
    for (int i = t; i < 2*64*9; i += 256) ws[i] = w[ocg*2*576 + i];
    float acc[4][2];
    #pragma unroll
    for (int i=0;i<4;i++){ acc[i][0]=0.f; acc[i][1]=0.f; }
    for (int ic = 0; ic < 64; ++ic){
        __syncthreads();
        const float* xp = x + (((size_t)b*64+ic)<<12);
        for (int i = t; i < 4096; i += 256) xs[i] = xp[i];
        __syncthreads();
        #pragma unroll
        for (int i=0;i<4;i++){
            int p  = i*256 + t;
            int oy = p>>5, ox = p&31;
            int iy0 = 2*oy-1, ix0 = 2*ox-1;
            float xv[9];
            #pragma unroll
            for (int ky=0;ky<3;ky++)
                #pragma unroll
                for (int kx=0;kx<3;kx++){
                    int iy=iy0+ky, ix=ix0+kx;
                    xv[ky*3+kx] = (iy>=0&&iy<64&&ix>=0&&ix<64)? xs[(iy<<6)+ix] : 0.0f;
                }
            #pragma unroll
            for (int ol=0;ol<2;ol++){
                const float* wp = ws + ol*576 + ic*9;
                float s = acc[i][ol];
                #pragma unroll
                for (int k=0;k<9;k++) s += xv[k]*wp[k];
                acc[i][ol] = s;
            }
        }
    }
    #pragma unroll
    for (int ol=0;ol<2;ol++){
        int oc = ocg*2+ol;
        float bv = bias[oc];
        #pragma unroll
        for (int i=0;i<4;i++){
            int p = i*256+t;
            float v = acc[i][ol]+bv;
            g_f1[(((b*64)+oc)<<10)+p] = v>0.f? v : 0.f;
        }
    }
}

// ---------------- conv2 + relu + spatial mean: f1 -> f2[4,128] ----------------
__global__ void conv2_kernel(const float* __restrict__ w,
                             const float* __restrict__ bias){
    const int oc = blockIdx.x;   // 0..127
    const int b  = blockIdx.y;
    const int t  = threadIdx.x;  // 256, one output pixel each (16x16)
    __shared__ float xs[32*32];
    __shared__ float ws[64*9];
    __shared__ float red[256];
    for (int i=t;i<576;i+=256) ws[i]=w[oc*576+i];
    int oy=t>>4, ox=t&15;
    int iy0=2*oy-1, ix0=2*ox-1;
    float acc=0.f;
    for (int ic=0;ic<64;++ic){
        __syncthreads();
        const float* xp = g_f1 + (((b*64)+ic)<<10);
        for (int i=t;i<1024;i+=256) xs[i]=xp[i];
        __syncthreads();
        const float* wp = ws + ic*9;
        #pragma unroll
        for (int ky=0;ky<3;ky++)
            #pragma unroll
            for (int kx=0;kx<3;kx++){
                int iy=iy0+ky, ix=ix0+kx;
                float xv = (iy>=0&&iy<32&&ix>=0&&ix<32)? xs[(iy<<5)+ix] : 0.0f;
                acc += xv*wp[ky*3+kx];
            }
    }
    acc += bias[oc];
    acc = acc>0.f? acc : 0.f;
    red[t]=acc; __syncthreads();
    for (int s=128;s>0;s>>=1){ if(t<s) red[t]+=red[t+s]; __syncthreads(); }
    if (t==0) g_f2[b*128+oc] = red[0]*(1.0f/256.0f);
}

// ---------------- fc + argmax -> branch id per sample ----------------
__global__ void fc_argmax_kernel(const float* __restrict__ fcw,
                                 const float* __restrict__ fcb){
    int wid = threadIdx.x>>5, lane = threadIdx.x&31;
    if (wid >= BB) return;
    float v = -1e30f; int idx = lane;
    if (lane < 25){
        float s = fcb[lane];
        const float* f2   = g_f2 + wid*128;
        const float* wrow = fcw  + lane*128;
        #pragma unroll 4
        for (int k=0;k<128;k++) s += f2[k]*wrow[k];
        v = s;
    }
    #pragma unroll
    for (int off=16;off>0;off>>=1){
        float ov = __shfl_down_sync(0xffffffffu, v,   off);
        int   oi = __shfl_down_sync(0xffffffffu, idx, off);
        if (ov > v || (ov==v && oi<idx)){ v=ov; idx=oi; }
    }
    if (lane==0) g_branch[wid] = c_branch_tab[idx];
}

// ---------------- QKV projections (1x1 convs), split across 2 thread-halves ----------------
__global__ void __launch_bounds__(256) qkv_kernel(const float* __restrict__ x,
    const float* __restrict__ wq, const float* __restrict__ bq,
    const float* __restrict__ wk, const float* __restrict__ bk,
    const float* __restrict__ wv, const float* __restrict__ bv){
    __shared__ __align__(16) float wqt[64*8];
    __shared__ __align__(16) float wkt[64*8];
    __shared__ __align__(16) float wvt[64*64];
    const int t = threadIdx.x;   // 256
    for (int i=t;i<512;i+=256){ int o=i>>6,c=i&63; wqt[c*8+o]=wq[i]; wkt[c*8+o]=wk[i]; }
    for (int i=t;i<4096;i+=256){ int o=i>>6,c=i&63; wvt[c*64+o]=wv[i]; }
    __syncthreads();
    const int b    = blockIdx.y;
    const int half = t>>7;            // 0: V[0:32]+Q, 1: V[32:64]+K
    const int nl   = t&127;
    const int n    = blockIdx.x*128 + nl;
    float av[32], aqk[8];
    const float* bqk = half? bk : bq;
    #pragma unroll
    for (int o=0;o<32;o++) av[o]=bv[half*32+o];
    #pragma unroll
    for (int o=0;o<8;o++) aqk[o]=bqk[o];
    const float* wqkt = half? wkt : wqt;
    const float* xb = x + (size_t)b*CC*HWD + n;
    for (int c=0;c<64;c++){
        float xc = xb[(size_t)c*HWD];
        const float4* wv4 = (const float4*)(wvt + c*64 + half*32);
        #pragma unroll
        for (int j=0;j<8;j++){
            float4 v = wv4[j];
            av[4*j+0]+=v.x*xc; av[4*j+1]+=v.y*xc; av[4*j+2]+=v.z*xc; av[4*j+3]+=v.w*xc;
        }
        const float4* wq4 = (const float4*)(wqkt + c*8);
        #pragma unroll
        for (int j=0;j<2;j++){
            float4 q4=wq4[j];
            aqk[4*j+0]+=q4.x*xc; aqk[4*j+1]+=q4.y*xc; aqk[4*j+2]+=q4.z*xc; aqk[4*j+3]+=q4.w*xc;
        }
    }
    #pragma unroll
    for (int o=0;o<32;o++) g_V[((b<<6)+half*32+o)*HWD + n] = av[o];
    float* gqk = half? g_K : g_Q;
    #pragma unroll
    for (int o=0;o<8;o++) gqk[((b<<3)+o)*HWD + n] = aqk[o];
}

// ---------------- sobel / hsv / hist maps ----------------
__global__ void spatial3_kernel(const float* __restrict__ x){
    int id = blockIdx.x*128 + threadIdx.x;  // 16384 threads
    int b = id>>12, p = id&4095;
    int y = p>>6, xw = p&63;
    float ssum=0.f, csum=0.f, mx=-1e30f, mn=1e30f;
    const float* xb = x + ((size_t)b<<18);
    for (int c=0;c<64;c++){
        const float* xp = xb + (c<<12);
        float v[3][3];
        #pragma unroll
        for (int dy=-1;dy<=1;dy++)
            #pragma unroll
            for (int dx=-1;dx<=1;dx++){
                int yy=y+dy, xx=xw+dx;
                v[dy+1][dx+1] = (yy>=0&&yy<64&&xx>=0&&xx<64)? xp[(yy<<6)+xx] : 0.0f;
            }
        float gx = (v[0][2]+2.f*v[1][2]+v[2][2]) - (v[0][0]+2.f*v[1][0]+v[2][0]);
        float gy = (v[2][0]+2.f*v[2][1]+v[2][2]) - (v[0][0]+2.f*v[0][1]+v[0][2]);
        ssum += sqrtf(gx*gx+gy*gy);
        float ctr = v[1][1];
        csum += ctr; mx = fmaxf(mx,ctr); mn = fminf(mn,ctr);
    }
    g_sobel[id] = sigmoidf_(ssum*(1.0f/64.0f));
    g_hsv[id]   = (mx-mn+1e-6f)/(mx+1e-6f);
    g_hist[id]  = sigmoidf_(csum*(1.0f/64.0f));
}

// ---------------- 64x64 DFT magnitude (fftshifted) per (b,c) ----------------
__global__ void fft_kernel(const float* __restrict__ x){
    extern __shared__ float sm[];
    float* xs  = sm;            // 4096 real input
    float* re  = sm + 4096;     // 4096 row-FFT real
    float* im  = sm + 8192;     // 4096 row-FFT imag
    float* twc = sm + 12288;    // 64 cos
    float* tws = sm + 12352;    // 64 sin
    const int c = blockIdx.x, b = blockIdx.y;
    const int t = threadIdx.x;  // 256
    const float* xp = x + ((size_t)(((b<<6)+c))<<12);
    for (int i=t;i<4096;i+=256) xs[i]=xp[i];
    if (t<64){ float s,co; sincosf(-6.283185307179586f * (float)t * (1.0f/64.0f), &s, &co); twc[t]=co; tws[t]=s; }
    __syncthreads();
    for (int o=t;o<4096;o+=256){
        int r=o>>6, v=o&63;
        const float* row = xs + (r<<6);
        float cr=0.f, ci=0.f;
        #pragma unroll 4
        for (int j=0;j<64;j++){
            int ti = (v*j)&63;
            float xv = row[j];
            cr += xv*twc[ti];
            ci += xv*tws[ti];
        }
        re[o]=cr; im[o]=ci;
    }
    __syncthreads();
    float* outp = g_fftmag + ((size_t)(((b<<6)+c))<<12);
    for (int o=t;o<4096;o+=256){
        int u=o>>6, v=o&63;
        float fr=0.f, fi=0.f;
        #pragma unroll 4
        for (int r=0;r<64;r++){
            int ti=(u*r)&63;
            float a = re[(r<<6)+v], bm = im[(r<<6)+v];
            float tc=twc[ti], ts=tws[ti];
            fr += a*tc - bm*ts;
            fi += a*ts + bm*tc;
        }
        float mag = sqrtf(fr*fr+fi*fi);
        int su=(u+32)&63, sv=(v+32)&63;
        outp[(su<<6)+sv]=mag;
    }
}

// ---------------- select map per sample by branch, scale by spatial_weight ----------------
__global__ void combine_kernel(const float* __restrict__ swp){
    int id = blockIdx.x*256+threadIdx.x;  // 16384
    int b = id>>12, p = id&4095;
    int br = g_branch[b];
    float v;
    if      (br==0) v = g_sobel[id];
    else if (br==1) v = g_hsv[id];
    else if (br==2) v = g_hist[id];
    else {
        float s=0.f;
        const float* mp = g_fftmag + ((size_t)b<<18) + p;
        #pragma unroll 4
        for (int c=0;c<64;c++) s += mp[(size_t)c<<12];
        v = sigmoidf_(s*(1.0f/64.0f));
    }
    g_spatial[id] = swp[0]*v;
}

// ---------------- two-phase tiled flash attention + epilogue ----------------
// block: 256 threads, 128 queries (blockIdx.x), batch = blockIdx.y
// smem: Ks[8*128] | Vs[64*132] | Ps[128*128] | dsm[256]
// phase1: thread (q = t&127, mh = t>>7) computes e = exp(q.k) for 64 m, writes Ps
// phase2: thread (mh = t>>7, qg = (t>>3)&15, cg = t&7) owns 8q x 8c, f32x2 PV
__global__ void __launch_bounds__(256) attention_kernel(const float* __restrict__ x,
                                                        float* __restrict__ out){
    extern __shared__ float asm_[];
    float* Ks  = asm_;               // 1024
    float* Vs  = asm_ + 1024;        // 8448 (stride 132)
    float* Ps  = asm_ + 9472;        // 16384
    float* dsm = asm_ + 25856;       // 256
    const int t  = threadIdx.x;
    const int b  = blockIdx.y;
    const int n0 = blockIdx.x*128;

    const int q1  = t&127, mh = t>>7;       // phase1 roles
    const int qg  = (t>>3)&15, cg = t&7;    // phase2 roles

    float qd[8];
    #pragma unroll
    for (int d=0;d<8;d++) qd[d] = g_Q[((b<<3)+d)*HWD + n0 + q1] * 0.35355339059327373f;

    unsigned long long acc2[32];
    #pragma unroll
    for (int i=0;i<32;i++) acc2[i]=0ull;
    float dpart = 0.f;

    for (int kt=0;kt<32;kt++){
        const int m0 = kt<<7;
        __syncthreads();
        for (int i=t;i<1024;i+=256) Ks[i] = g_K[((b<<3)+(i>>7))*HWD + m0 + (i&127)];
        for (int i=t;i<8192;i+=256){ int c=i>>7, m=i&127; Vs[c*132+m] = g_V[((b<<6)+c)*HWD + m0+m]; }
        __syncthreads();
        // phase 1: scores -> exp -> Ps
        {
            const int mb = mh<<6;
            #pragma unroll 2
            for (int mm=mb; mm<mb+64; ++mm){
                float s = qd[0]*Ks[mm];
                #pragma unroll
                for (int d=1;d<8;d++) s += qd[d]*Ks[(d<<7)+mm];
                float e = __expf(s);
                dpart += e;
                Ps[(mm<<7) + q1] = e;
            }
        }
        __syncthreads();
        // phase 2: PV with f32x2, 8q x 8c per thread
        {
            const int mb = mh<<6;
            #pragma unroll 2
            for (int mm=mb; mm<mb+64; ++mm){
                const unsigned long long* pp =
                    (const unsigned long long*)(Ps + (mm<<7) + (qg<<3));
                unsigned long long e0=pp[0], e1=pp[1], e2=pp[2], e3=pp[3];
                unsigned long long vd[8];
                #pragma unroll
                for (int i=0;i<8;i++) vd[i] = dup2_(Vs[(cg+(i<<3))*132 + mm]);
                #pragma unroll
                for (int i=0;i<8;i++){
                    fma2_(acc2[ 0+i], vd[i], e0);
                    fma2_(acc2[ 8+i], vd[i], e1);
                    fma2_(acc2[16+i], vd[i], e2);
                    fma2_(acc2[24+i], vd[i], e3);
                }
            }
        }
    }
    // denom reduction + cross-half acc combine (staged through Ps)
    dsm[t] = dpart;
    __syncthreads();
    if (t >= 128){
        float* stg = Ps + ((t-128)<<6);
        #pragma unroll
        for (int k=0;k<32;k++){
            float lo,hi; unpack2_(acc2[k], lo, hi);
            stg[2*k]=lo; stg[2*k+1]=hi;
        }
    }
    __syncthreads();
    if (t < 128){
        const float* stg = Ps + (t<<6);
        float scl[8];
        #pragma unroll
        for (int qi=0;qi<8;qi++){
            int q = (qg<<3)+qi;
            float den = dsm[q] + dsm[q+128];
            scl[qi] = g_spatial[(b<<12) + n0 + q] / den;
        }
        #pragma unroll
        for (int i=0;i<8;i++){
            int c = cg + (i<<3);
            const float* xr = x   + ((size_t)b<<18) + ((size_t)c<<12) + n0 + (qg<<3);
            float*       orow = out + ((size_t)b<<18) + ((size_t)c<<12) + n0 + (qg<<3);
            float o[8];
            #pragma unroll
            for (int p=0;p<4;p++){
                float lo,hi; unpack2_(acc2[p*8+i], lo, hi);
                o[2*p]   = lo + stg[2*(p*8+i)];
                o[2*p+1] = hi + stg[2*(p*8+i)+1];
            }
            float4 x0 = *(const float4*)(xr);
            float4 x1 = *(const float4*)(xr+4);
            float4 r0, r1;
            r0.x = o[0]*scl[0] + x0.x;  r0.y = o[1]*scl[1] + x0.y;
            r0.z = o[2]*scl[2] + x0.z;  r0.w = o[3]*scl[3] + x0.w;
            r1.x = o[4]*scl[4] + x1.x;  r1.y = o[5]*scl[5] + x1.y;
            r1.z = o[6]*scl[6] + x1.z;  r1.w = o[7]*scl[7] + x1.w;
            *(float4*)(orow)   = r0;
            *(float4*)(orow+4) = r1;
        }
    }
}

// ---------------- launch ----------------
extern "C" void kernel_launch(void* const* d_in, const int* in_sizes, int n_in,
                              void* d_out, int out_size){
    const float* x    = (const float*)d_in[0];
    const float* wq   = (const float*)d_in[1];
    const float* bq   = (const float*)d_in[2];
    const float* wk   = (const float*)d_in[3];
    const float* bk   = (const float*)d_in[4];
    const float* wv   = (const float*)d_in[5];
    const float* bv   = (const float*)d_in[6];
    const float* c1w  = (const float*)d_in[7];
    const float* c1b  = (const float*)d_in[8];
    const float* c2w  = (const float*)d_in[9];
    const float* c2b  = (const float*)d_in[10];
    const float* fcw  = (const float*)d_in[11];
    const float* fcb  = (const float*)d_in[12];
    const float* swp  = (const float*)d_in[13];
    float* out = (float*)d_out;

    cudaFuncSetAttribute(fft_kernel, cudaFuncAttributeMaxDynamicSharedMemorySize, 49664);
    cudaFuncSetAttribute(attention_kernel, cudaFuncAttributeMaxDynamicSharedMemorySize, 104448);

    conv1_kernel   <<<dim3(32,4), 256>>>(x, c1w, c1b);
    conv2_kernel   <<<dim3(128,4),256>>>(c2w, c2b);
    fc_argmax_kernel<<<1,128>>>(fcw, fcb);
    qkv_kernel     <<<dim3(32,4), 256>>>(x, wq,bq, wk,bk, wv,bv);
    spatial3_kernel<<<128,128>>>(x);
    fft_kernel     <<<dim3(64,4), 256, 49664>>>(x);
    combine_kernel <<<64,256>>>(swp);
    attention_kernel<<<dim3(32,4),256, 104448>>>(x, out);
}

// round 3
// speedup vs baseline: 2.5828x; 1.9489x over previous
#include <cuda_runtime.h>
#include <cuda_bf16.h>

#define BB   4
#define CC   64
#define HWD  4096
#define QKD  8

// ---------------- device scratch ----------------
__device__ unsigned       g_Qh[BB*4*HWD];   // bf16x2 pairs: [b][dpair][n], exp-scale folded in
__device__ unsigned       g_Kh[BB*4*HWD];   // bf16x2 pairs: [b][dpair][n]
__device__ __nv_bfloat16  g_Vh[BB*CC*HWD];  // [b][c][m]
__device__ float g_f1[BB*64*32*32];
__device__ float g_f2[BB*128];
__device__ int   g_branch[BB];
__device__ float g_sobel[BB*HWD];
__device__ float g_hsv[BB*HWD];
__device__ float g_hist[BB*HWD];
__device__ float g_fftmag[BB*CC*HWD];
__device__ float g_spatial[BB*HWD];

__device__ const int c_branch_tab[25] =
    {0,0,0,0,0,0,1,1,0,0,0,0,0,0,3,1,1,2,3,0,0,3,3,3,3};

__device__ __forceinline__ float sigmoidf_(float z){ return 1.0f/(1.0f+__expf(-z)); }
__device__ __forceinline__ unsigned pack_bf16x2(float hi, float lo){
    unsigned r; asm("cvt.rn.bf16x2.f32 %0, %1, %2;" : "=r"(r) : "f"(hi), "f"(lo)); return r;
}
__device__ __forceinline__ float ex2_(float v){
    float r; asm("ex2.approx.f32 %0, %1;" : "=f"(r) : "f"(v)); return r;
}

// ---------------- classifier conv1: x -> relu -> f1[4,64,32,32] ----------------
__global__ void conv1_kernel(const float* __restrict__ x,
                             const float* __restrict__ w,
                             const float* __restrict__ bias){
    const int ocg = blockIdx.x, b = blockIdx.y, t = threadIdx.x;
    __shared__ float xs[64*64];
    __shared__ float ws[2*64*9];
    for (int i = t; i < 2*64*9; i += 256) ws[i] = w[ocg*2*576 + i];
    float acc[4][2];
    #pragma unroll
    for (int i=0;i<4;i++){ acc[i][0]=0.f; acc[i][1]=0.f; }
    for (int ic = 0; ic < 64; ++ic){
        __syncthreads();
        const float* xp = x + (((size_t)b*64+ic)<<12);
        for (int i = t; i < 4096; i += 256) xs[i] = xp[i];
        __syncthreads();
        #pragma unroll
        for (int i=0;i<4;i++){
            int p  = i*256 + t;
            int oy = p>>5, ox = p&31;
            int iy0 = 2*oy-1, ix0 = 2*ox-1;
            float xv[9];
            #pragma unroll
            for (int ky=0;ky<3;ky++)
                #pragma unroll
                for (int kx=0;kx<3;kx++){
                    int iy=iy0+ky, ix=ix0+kx;
                    xv[ky*3+kx] = (iy>=0&&iy<64&&ix>=0&&ix<64)? xs[(iy<<6)+ix] : 0.0f;
                }
            #pragma unroll
            for (int ol=0;ol<2;ol++){
                const float* wp = ws + ol*576 + ic*9;
                float s = acc[i][ol];
                #pragma unroll
                for (int k=0;k<9;k++) s += xv[k]*wp[k];
                acc[i][ol] = s;
            }
        }
    }
    #pragma unroll
    for (int ol=0;ol<2;ol++){
        int oc = ocg*2+ol;
        float bv = bias[oc];
        #pragma unroll
        for (int i=0;i<4;i++){
            int p = i*256+t;
            float v = acc[i][ol]+bv;
            g_f1[(((b*64)+oc)<<10)+p] = v>0.f? v : 0.f;
        }
    }
}

// ---------------- conv2 + relu + spatial mean ----------------
__global__ void conv2_kernel(const float* __restrict__ w,
                             const float* __restrict__ bias){
    const int oc = blockIdx.x, b = blockIdx.y, t = threadIdx.x;
    __shared__ float xs[32*32];
    __shared__ float ws[64*9];
    __shared__ float red[256];
    for (int i=t;i<576;i+=256) ws[i]=w[oc*576+i];
    int oy=t>>4, ox=t&15;
    int iy0=2*oy-1, ix0=2*ox-1;
    float acc=0.f;
    for (int ic=0;ic<64;++ic){
        __syncthreads();
        const float* xp = g_f1 + (((b*64)+ic)<<10);
        for (int i=t;i<1024;i+=256) xs[i]=xp[i];
        __syncthreads();
        const float* wp = ws + ic*9;
        #pragma unroll
        for (int ky=0;ky<3;ky++)
            #pragma unroll
            for (int kx=0;kx<3;kx++){
                int iy=iy0+ky, ix=ix0+kx;
                float xv = (iy>=0&&iy<32&&ix>=0&&ix<32)? xs[(iy<<5)+ix] : 0.0f;
                acc += xv*wp[ky*3+kx];
            }
    }
    acc += bias[oc];
    acc = acc>0.f? acc : 0.f;
    red[t]=acc; __syncthreads();
    for (int s=128;s>0;s>>=1){ if(t<s) red[t]+=red[t+s]; __syncthreads(); }
    if (t==0) g_f2[b*128+oc] = red[0]*(1.0f/256.0f);
}

// ---------------- fc + argmax ----------------
__global__ void fc_argmax_kernel(const float* __restrict__ fcw,
                                 const float* __restrict__ fcb){
    int wid = threadIdx.x>>5, lane = threadIdx.x&31;
    if (wid >= BB) return;
    float v = -1e30f; int idx = lane;
    if (lane < 25){
        float s = fcb[lane];
        const float* f2   = g_f2 + wid*128;
        const float* wrow = fcw  + lane*128;
        #pragma unroll 4
        for (int k=0;k<128;k++) s += f2[k]*wrow[k];
        v = s;
    }
    #pragma unroll
    for (int off=16;off>0;off>>=1){
        float ov = __shfl_down_sync(0xffffffffu, v,   off);
        int   oi = __shfl_down_sync(0xffffffffu, idx, off);
        if (ov > v || (ov==v && oi<idx)){ v=ov; idx=oi; }
    }
    if (lane==0) g_branch[wid] = c_branch_tab[idx];
}

// ---------------- QKV projections -> bf16 packed layouts ----------------
__global__ void __launch_bounds__(128) qkv_kernel(const float* __restrict__ x,
    const float* __restrict__ wq, const float* __restrict__ bq,
    const float* __restrict__ wk, const float* __restrict__ bk,
    const float* __restrict__ wv, const float* __restrict__ bv){
    __shared__ __align__(16) float wqt[64*8];
    __shared__ __align__(16) float wkt[64*8];
    __shared__ __align__(16) float wvt[64*64];
    const int t = threadIdx.x;   // 128
    for (int i=t;i<512;i+=128){ int o=i>>6,c=i&63; wqt[c*8+o]=wq[i]; wkt[c*8+o]=wk[i]; }
    for (int i=t;i<4096;i+=128){ int o=i>>6,c=i&63; wvt[c*64+o]=wv[i]; }
    __syncthreads();
    const int b    = blockIdx.y;
    const int half = t>>6;            // 0: V[0:32]+Q, 1: V[32:64]+K
    const int nl   = t&63;
    const int n    = blockIdx.x*64 + nl;
    float av[32], aqk[8];
    const float* bqk = half? bk : bq;
    #pragma unroll
    for (int o=0;o<32;o++) av[o]=bv[half*32+o];
    #pragma unroll
    for (int o=0;o<8;o++) aqk[o]=bqk[o];
    const float* wqkt = half? wkt : wqt;
    const float* xb = x + (size_t)b*CC*HWD + n;
    for (int c=0;c<64;c++){
        float xc = xb[(size_t)c*HWD];
        const float4* wv4 = (const float4*)(wvt + c*64 + half*32);
        #pragma unroll
        for (int j=0;j<8;j++){
            float4 v = wv4[j];
            av[4*j+0]+=v.x*xc; av[4*j+1]+=v.y*xc; av[4*j+2]+=v.z*xc; av[4*j+3]+=v.w*xc;
        }
        const float4* wq4 = (const float4*)(wqkt + c*8);
        #pragma unroll
        for (int j=0;j<2;j++){
            float4 q4=wq4[j];
            aqk[4*j+0]+=q4.x*xc; aqk[4*j+1]+=q4.y*xc; aqk[4*j+2]+=q4.z*xc; aqk[4*j+3]+=q4.w*xc;
        }
    }
    #pragma unroll
    for (int o=0;o<32;o++)
        g_Vh[((size_t)((b<<6)+half*32+o))*HWD + n] = __float2bfloat16(av[o]);
    // Q gets softmax-scale * log2(e) folded in; K unscaled
    const float f = half? 1.0f : (0.35355339059327373f * 1.4426950408889634f);
    unsigned* dst = half? g_Kh : g_Qh;
    #pragma unroll
    for (int dp=0;dp<4;dp++)
        dst[((b<<2)+dp)*HWD + n] = pack_bf16x2(aqk[2*dp+1]*f, aqk[2*dp]*f);
}

// ---------------- sobel / hsv / hist maps (smem-tiled, dbl-buffered channels) ----------------
__global__ void __launch_bounds__(128) spatial3_kernel(const float* __restrict__ x){
    __shared__ float xs[2][4][64];
    const int b = blockIdx.y, y0 = blockIdx.x*2;
    const int t = threadIdx.x, ty = t>>6, tx = t&63;
    const int y = y0 + ty;
    const float* xb = x + ((size_t)b<<18);
    float ssum=0.f, csum=0.f, mx=-1e30f, mn=1e30f;
    #pragma unroll
    for (int i=t;i<256;i+=128){
        int r=i>>6, xx=i&63, yy=y0-1+r;
        xs[0][r][xx] = (yy>=0&&yy<64)? xb[(yy<<6)+xx] : 0.f;
    }
    __syncthreads();
    for (int c=0;c<64;c++){
        if (c+1<64){
            const float* xp = xb + ((size_t)(c+1)<<12);
            #pragma unroll
            for (int i=t;i<256;i+=128){
                int r=i>>6, xx=i&63, yy=y0-1+r;
                xs[(c+1)&1][r][xx] = (yy>=0&&yy<64)? xp[(yy<<6)+xx] : 0.f;
            }
        }
        const float (*cur)[64] = xs[c&1];
        float v[3][3];
        #pragma unroll
        for (int dy=0;dy<3;dy++)
            #pragma unroll
            for (int dx=-1;dx<=1;dx++){
                int xx=tx+dx;
                v[dy][dx+1] = (xx>=0&&xx<64)? cur[ty+dy][xx] : 0.f;
            }
        float gx = (v[0][2]+2.f*v[1][2]+v[2][2]) - (v[0][0]+2.f*v[1][0]+v[2][0]);
        float gy = (v[2][0]+2.f*v[2][1]+v[2][2]) - (v[0][0]+2.f*v[0][1]+v[0][2]);
        ssum += sqrtf(gx*gx+gy*gy);
        float ctr = v[1][1];
        csum += ctr; mx = fmaxf(mx,ctr); mn = fminf(mn,ctr);
        __syncthreads();
    }
    int id = (b<<12) + (y<<6) + tx;
    g_sobel[id] = sigmoidf_(ssum*(1.0f/64.0f));
    g_hsv[id]   = (mx-mn+1e-6f)/(mx+1e-6f);
    g_hist[id]  = sigmoidf_(csum*(1.0f/64.0f));
}

// ---------------- 64x64 DFT magnitude, gated per-sample on branch==3 ----------------
__global__ void fft_kernel(const float* __restrict__ x){
    const int c = blockIdx.x, b = blockIdx.y;
    if (g_branch[b] != 3) return;
    extern __shared__ float sm[];
    float* xs  = sm;
    float* re  = sm + 4096;
    float* im  = sm + 8192;
    float* twc = sm + 12288;
    float* tws = sm + 12352;
    const int t = threadIdx.x;
    const float* xp = x + ((size_t)(((b<<6)+c))<<12);
    for (int i=t;i<4096;i+=256) xs[i]=xp[i];
    if (t<64){ float s,co; sincosf(-6.283185307179586f * (float)t * (1.0f/64.0f), &s, &co); twc[t]=co; tws[t]=s; }
    __syncthreads();
    for (int o=t;o<4096;o+=256){
        int r=o>>6, v=o&63;
        const float* row = xs + (r<<6);
        float cr=0.f, ci=0.f;
        #pragma unroll 4
        for (int j=0;j<64;j++){
            int ti = (v*j)&63;
            float xv = row[j];
            cr += xv*twc[ti];
            ci += xv*tws[ti];
        }
        re[o]=cr; im[o]=ci;
    }
    __syncthreads();
    float* outp = g_fftmag + ((size_t)(((b<<6)+c))<<12);
    for (int o=t;o<4096;o+=256){
        int u=o>>6, v=o&63;
        float fr=0.f, fi=0.f;
        #pragma unroll 4
        for (int r=0;r<64;r++){
            int ti=(u*r)&63;
            float a = re[(r<<6)+v], bm = im[(r<<6)+v];
            float tc=twc[ti], ts=tws[ti];
            fr += a*tc - bm*ts;
            fi += a*ts + bm*tc;
        }
        float mag = sqrtf(fr*fr+fi*fi);
        int su=(u+32)&63, sv=(v+32)&63;
        outp[(su<<6)+sv]=mag;
    }
}

// ---------------- select map per sample, scale by spatial_weight ----------------
__global__ void combine_kernel(const float* __restrict__ swp){
    int id = blockIdx.x*256+threadIdx.x;
    int b = id>>12, p = id&4095;
    int br = g_branch[b];
    float v;
    if      (br==0) v = g_sobel[id];
    else if (br==1) v = g_hsv[id];
    else if (br==2) v = g_hist[id];
    else {
        float s=0.f;
        const float* mp = g_fftmag + ((size_t)b<<18) + p;
        #pragma unroll 4
        for (int c=0;c<64;c++) s += mp[(size_t)c<<12];
        v = sigmoidf_(s*(1.0f/64.0f));
    }
    g_spatial[id] = swp[0]*v;
}

// ---------------- tensor-core flash attention + routed epilogue ----------------
// grid (64, 4): 64 queries per block, 4 warps (warp w owns 16 q).
// smem: Ksu[4][136] u32 (bf16x2 d-pairs x m)  |  Vsu[64][68] u32 (bf16 pairs along m)
//       Osm[64][68] f32 overlays Vsu after the mainloop.
// mma1: S[16q x 8m] = Q(bf16,k=16, d 8..15 zero) x K ; C-frag -> exp2 -> bf16 A-frag of
// mma2: O[16q x 8c] += P(16x16) x V(16m x 8c).
__global__ void __launch_bounds__(128) attention_kernel(const float* __restrict__ x,
                                                        float* __restrict__ out){
    extern __shared__ char sm8[];
    unsigned* Ksu = (unsigned*)sm8;               // 4*136 u32 = 2176 B
    unsigned* Vsu = (unsigned*)(sm8 + 2176);      // 64*68 u32 = 17408 B
    float*    Osm = (float*)(sm8 + 2176);         // overlays Vsu
    const int t = threadIdx.x, lane = t&31, w = t>>5;
    const int g = lane>>2, l = lane&3;
    const int b = blockIdx.y, n0 = blockIdx.x*64;
    const int qw = w*16;

    // Q fragment (A of mma1): rows qw+g / qw+g+8, k-cols 2l,2l+1 (d), 8..15 zero
    unsigned qa0 = g_Qh[((b<<2)+l)*HWD + n0 + qw + g];
    unsigned qa1 = g_Qh[((b<<2)+l)*HWD + n0 + qw + g + 8];
    const unsigned zz = 0u;

    float o[32];
    #pragma unroll
    for (int i=0;i<32;i++) o[i]=0.f;
    float d0=0.f, d1=0.f;

    for (int kt=0;kt<32;kt++){
        const int m0 = kt<<7;
        __syncthreads();
        // stage K: 4 dpair-rows x 32 uint4 (128 u32)
        {
            int dp = t>>5, j = t&31;
            ((uint4*)(Ksu + dp*136))[j] =
                ((const uint4*)(g_Kh + ((b<<2)+dp)*HWD + m0))[j];
        }
        // stage V: 64 c-rows x 16 uint4
        for (int i=t;i<1024;i+=128){
            int r = i>>4, j = i&15;
            ((uint4*)(Vsu + r*68))[j] =
                ((const uint4*)(g_Vh + ((size_t)((b<<6)+r))*HWD + m0))[j];
        }
        __syncthreads();

        #pragma unroll 2
        for (int mc=0;mc<8;mc++){
            const int m16 = mc<<4;
            float s0,s1,s2,s3,s4,s5,s6,s7;
            unsigned kb0 = Ksu[l*136 + m16 + g];
            unsigned kb1 = Ksu[l*136 + m16 + 8 + g];
            asm("mma.sync.aligned.m16n8k16.row.col.f32.bf16.bf16.f32 "
                "{%0,%1,%2,%3},{%4,%5,%6,%7},{%8,%9},{%10,%11,%12,%13};"
                : "=f"(s0),"=f"(s1),"=f"(s2),"=f"(s3)
                : "r"(qa0),"r"(qa1),"r"(zz),"r"(zz), "r"(kb0),"r"(zz),
                  "f"(0.f),"f"(0.f),"f"(0.f),"f"(0.f));
            asm("mma.sync.aligned.m16n8k16.row.col.f32.bf16.bf16.f32 "
                "{%0,%1,%2,%3},{%4,%5,%6,%7},{%8,%9},{%10,%11,%12,%13};"
                : "=f"(s4),"=f"(s5),"=f"(s6),"=f"(s7)
                : "r"(qa0),"r"(qa1),"r"(zz),"r"(zz), "r"(kb1),"r"(zz),
                  "f"(0.f),"f"(0.f),"f"(0.f),"f"(0.f));
            s0=ex2_(s0); s1=ex2_(s1); s2=ex2_(s2); s3=ex2_(s3);
            s4=ex2_(s4); s5=ex2_(s5); s6=ex2_(s6); s7=ex2_(s7);
            d0 += (s0+s1)+(s4+s5);
            d1 += (s2+s3)+(s6+s7);
            unsigned p0 = pack_bf16x2(s1,s0);   // row g,   k 2l,2l+1
            unsigned p1 = pack_bf16x2(s3,s2);   // row g+8, k 2l,2l+1
            unsigned p2 = pack_bf16x2(s5,s4);   // row g,   k 8+2l,+1
            unsigned p3 = pack_bf16x2(s7,s6);   // row g+8, k 8+2l,+1
            const int vbase = (m16>>1) + l;
            #pragma unroll
            for (int ct=0;ct<8;ct++){
                unsigned vb0 = Vsu[(ct*8+g)*68 + vbase];
                unsigned vb1 = Vsu[(ct*8+g)*68 + vbase + 4];
                asm("mma.sync.aligned.m16n8k16.row.col.f32.bf16.bf16.f32 "
                    "{%0,%1,%2,%3},{%4,%5,%6,%7},{%8,%9},{%0,%1,%2,%3};"
                    : "+f"(o[ct*4+0]),"+f"(o[ct*4+1]),"+f"(o[ct*4+2]),"+f"(o[ct*4+3])
                    : "r"(p0),"r"(p1),"r"(p2),"r"(p3), "r"(vb0),"r"(vb1));
            }
        }
    }
    // denom reduce across the 4 lanes sharing a row (lane%4 varies)
    d0 += __shfl_xor_sync(0xffffffffu, d0, 1);
    d0 += __shfl_xor_sync(0xffffffffu, d0, 2);
    d1 += __shfl_xor_sync(0xffffffffu, d1, 1);
    d1 += __shfl_xor_sync(0xffffffffu, d1, 2);
    const float scl0 = g_spatial[(b<<12) + n0 + qw + g    ] / d0;
    const float scl1 = g_spatial[(b<<12) + n0 + qw + g + 8] / d1;

    __syncthreads();   // all warps done reading Vsu before Osm overlay
    #pragma unroll
    for (int ct=0;ct<8;ct++){
        int c0 = ct*8 + 2*l;
        Osm[ c0   *68 + qw + g    ] = o[ct*4+0]*scl0;
        Osm[(c0+1)*68 + qw + g    ] = o[ct*4+1]*scl0;
        Osm[ c0   *68 + qw + g + 8] = o[ct*4+2]*scl1;
        Osm[(c0+1)*68 + qw + g + 8] = o[ct*4+3]*scl1;
    }
    __syncthreads();
    for (int i=t;i<4096;i+=128){
        int c = i>>6, q = i&63;
        size_t gi = ((size_t)((b<<6)+c)<<12) + n0 + q;
        out[gi] = Osm[c*68+q] + x[gi];
    }
}

// ---------------- launch ----------------
extern "C" void kernel_launch(void* const* d_in, const int* in_sizes, int n_in,
                              void* d_out, int out_size){
    const float* x    = (const float*)d_in[0];
    const float* wq   = (const float*)d_in[1];
    const float* bq   = (const float*)d_in[2];
    const float* wk   = (const float*)d_in[3];
    const float* bk   = (const float*)d_in[4];
    const float* wv   = (const float*)d_in[5];
    const float* bv   = (const float*)d_in[6];
    const float* c1w  = (const float*)d_in[7];
    const float* c1b  = (const float*)d_in[8];
    const float* c2w  = (const float*)d_in[9];
    const float* c2b  = (const float*)d_in[10];
    const float* fcw  = (const float*)d_in[11];
    const float* fcb  = (const float*)d_in[12];
    const float* swp  = (const float*)d_in[13];
    float* out = (float*)d_out;

    cudaFuncSetAttribute(fft_kernel, cudaFuncAttributeMaxDynamicSharedMemorySize, 49664);

    conv1_kernel    <<<dim3(32,4), 256>>>(x, c1w, c1b);
    conv2_kernel    <<<dim3(128,4),256>>>(c2w, c2b);
    fc_argmax_kernel<<<1,128>>>(fcw, fcb);
    qkv_kernel      <<<dim3(64,4), 128>>>(x, wq,bq, wk,bk, wv,bv);
    spatial3_kernel <<<dim3(32,4), 128>>>(x);
    fft_kernel      <<<dim3(64,4), 256, 49664>>>(x);
    combine_kernel  <<<64,256>>>(swp);
    attention_kernel<<<dim3(64,4), 128, 19584>>>(x, out);
}

// round 4
// speedup vs baseline: 2.9772x; 1.1527x over previous
#include <cuda_runtime.h>
#include <cuda_bf16.h>

#define BB   4
#define CC   64
#define HWD  4096
#define QKD  8
#define NSPL 4

// ---------------- device scratch ----------------
__device__ unsigned       g_Qh[BB*4*HWD];   // bf16x2 pairs: [b][dpair][n], exp-scale folded in
__device__ unsigned       g_Kh[BB*4*HWD];   // bf16x2 pairs: [b][dpair][n]
__device__ __nv_bfloat16  g_Vh[BB*CC*HWD];  // [b][c][m]
__device__ float g_Opart[NSPL*BB*CC*HWD];   // split partial O
__device__ float g_dpart[NSPL*BB*HWD];      // split partial denom
__device__ float g_f1[BB*64*32*32];
__device__ float g_f2[BB*128];
__device__ int   g_branch[BB];
__device__ float g_sobel[BB*HWD];
__device__ float g_hsv[BB*HWD];
__device__ float g_hist[BB*HWD];
__device__ float g_fftmag[BB*CC*HWD];
__device__ float g_spatial[BB*HWD];

__device__ const int c_branch_tab[25] =
    {0,0,0,0,0,0,1,1,0,0,0,0,0,0,3,1,1,2,3,0,0,3,3,3,3};

__device__ __forceinline__ float sigmoidf_(float z){ return 1.0f/(1.0f+__expf(-z)); }
__device__ __forceinline__ unsigned pack_bf16x2(float hi, float lo){
    unsigned r; asm("cvt.rn.bf16x2.f32 %0, %1, %2;" : "=r"(r) : "f"(hi), "f"(lo)); return r;
}
__device__ __forceinline__ float ex2_(float v){
    float r; asm("ex2.approx.f32 %0, %1;" : "=f"(r) : "f"(v)); return r;
}

// ---------------- classifier conv1: x -> relu -> f1[4,64,32,32] ----------------
__global__ void conv1_kernel(const float* __restrict__ x,
                             const float* __restrict__ w,
                             const float* __restrict__ bias){
    const int ocg = blockIdx.x, b = blockIdx.y, t = threadIdx.x;
    __shared__ float xs[64*64];
    __shared__ float ws[2*64*9];
    for (int i = t; i < 2*64*9; i += 256) ws[i] = w[ocg*2*576 + i];
    float acc[4][2];
    #pragma unroll
    for (int i=0;i<4;i++){ acc[i][0]=0.f; acc[i][1]=0.f; }
    for (int ic = 0; ic < 64; ++ic){
        __syncthreads();
        const float* xp = x + (((size_t)b*64+ic)<<12);
        for (int i = t; i < 4096; i += 256) xs[i] = xp[i];
        __syncthreads();
        #pragma unroll
        for (int i=0;i<4;i++){
            int p  = i*256 + t;
            int oy = p>>5, ox = p&31;
            int iy0 = 2*oy-1, ix0 = 2*ox-1;
            float xv[9];
            #pragma unroll
            for (int ky=0;ky<3;ky++)
                #pragma unroll
                for (int kx=0;kx<3;kx++){
                    int iy=iy0+ky, ix=ix0+kx;
                    xv[ky*3+kx] = (iy>=0&&iy<64&&ix>=0&&ix<64)? xs[(iy<<6)+ix] : 0.0f;
                }
            #pragma unroll
            for (int ol=0;ol<2;ol++){
                const float* wp = ws + ol*576 + ic*9;
                float s = acc[i][ol];
                #pragma unroll
                for (int k=0;k<9;k++) s += xv[k]*wp[k];
                acc[i][ol] = s;
            }
        }
    }
    #pragma unroll
    for (int ol=0;ol<2;ol++){
        int oc = ocg*2+ol;
        float bv = bias[oc];
        #pragma unroll
        for (int i=0;i<4;i++){
            int p = i*256+t;
            float v = acc[i][ol]+bv;
            g_f1[(((b*64)+oc)<<10)+p] = v>0.f? v : 0.f;
        }
    }
}

// ---------------- conv2 + relu + spatial mean ----------------
__global__ void conv2_kernel(const float* __restrict__ w,
                             const float* __restrict__ bias){
    const int oc = blockIdx.x, b = blockIdx.y, t = threadIdx.x;
    __shared__ float xs[32*32];
    __shared__ float ws[64*9];
    __shared__ float red[256];
    for (int i=t;i<576;i+=256) ws[i]=w[oc*576+i];
    int oy=t>>4, ox=t&15;
    int iy0=2*oy-1, ix0=2*ox-1;
    float acc=0.f;
    for (int ic=0;ic<64;++ic){
        __syncthreads();
        const float* xp = g_f1 + (((b*64)+ic)<<10);
        for (int i=t;i<1024;i+=256) xs[i]=xp[i];
        __syncthreads();
        const float* wp = ws + ic*9;
        #pragma unroll
        for (int ky=0;ky<3;ky++)
            #pragma unroll
            for (int kx=0;kx<3;kx++){
                int iy=iy0+ky, ix=ix0+kx;
                float xv = (iy>=0&&iy<32&&ix>=0&&ix<32)? xs[(iy<<5)+ix] : 0.0f;
                acc += xv*wp[ky*3+kx];
            }
    }
    acc += bias[oc];
    acc = acc>0.f? acc : 0.f;
    red[t]=acc; __syncthreads();
    for (int s=128;s>0;s>>=1){ if(t<s) red[t]+=red[t+s]; __syncthreads(); }
    if (t==0) g_f2[b*128+oc] = red[0]*(1.0f/256.0f);
}

// ---------------- fc + argmax ----------------
__global__ void fc_argmax_kernel(const float* __restrict__ fcw,
                                 const float* __restrict__ fcb){
    int wid = threadIdx.x>>5, lane = threadIdx.x&31;
    if (wid >= BB) return;
    float v = -1e30f; int idx = lane;
    if (lane < 25){
        float s = fcb[lane];
        const float* f2   = g_f2 + wid*128;
        const float* wrow = fcw  + lane*128;
        #pragma unroll 4
        for (int k=0;k<128;k++) s += f2[k]*wrow[k];
        v = s;
    }
    #pragma unroll
    for (int off=16;off>0;off>>=1){
        float ov = __shfl_down_sync(0xffffffffu, v,   off);
        int   oi = __shfl_down_sync(0xffffffffu, idx, off);
        if (ov > v || (ov==v && oi<idx)){ v=ov; idx=oi; }
    }
    if (lane==0) g_branch[wid] = c_branch_tab[idx];
}

// ---------------- QKV projections -> bf16 packed layouts (x tiled in smem) ----------------
__global__ void __launch_bounds__(128) qkv_kernel(const float* __restrict__ x,
    const float* __restrict__ wq, const float* __restrict__ bq,
    const float* __restrict__ wk, const float* __restrict__ bk,
    const float* __restrict__ wv, const float* __restrict__ bv){
    __shared__ __align__(16) float wqt[64*8];
    __shared__ __align__(16) float wkt[64*8];
    __shared__ __align__(16) float wvt[64*64];
    __shared__ __align__(16) float xs[64*64];   // [c][n] tile
    const int t = threadIdx.x;   // 128
    const int b = blockIdx.y;
    const int n0 = blockIdx.x*64;
    for (int i=t;i<512;i+=128){ int o=i>>6,c=i&63; wqt[c*8+o]=wq[i]; wkt[c*8+o]=wk[i]; }
    for (int i=t;i<4096;i+=128){ int o=i>>6,c=i&63; wvt[c*64+o]=wv[i]; }
    {
        const float* xb = x + (size_t)b*CC*HWD + n0;
        for (int i=t;i<4096;i+=128){ int c=i>>6, nl=i&63; xs[i] = xb[(size_t)c*HWD + nl]; }
    }
    __syncthreads();
    const int half = t>>6;            // 0: V[0:32]+Q, 1: V[32:64]+K
    const int nl   = t&63;
    const int n    = n0 + nl;
    float av[32], aqk[8];
    const float* bqk = half? bk : bq;
    #pragma unroll
    for (int o=0;o<32;o++) av[o]=bv[half*32+o];
    #pragma unroll
    for (int o=0;o<8;o++) aqk[o]=bqk[o];
    const float* wqkt = half? wkt : wqt;
    for (int c=0;c<64;c++){
        float xc = xs[(c<<6) + nl];
        const float4* wv4 = (const float4*)(wvt + c*64 + half*32);
        #pragma unroll
        for (int j=0;j<8;j++){
            float4 v = wv4[j];
            av[4*j+0]+=v.x*xc; av[4*j+1]+=v.y*xc; av[4*j+2]+=v.z*xc; av[4*j+3]+=v.w*xc;
        }
        const float4* wq4 = (const float4*)(wqkt + c*8);
        #pragma unroll
        for (int j=0;j<2;j++){
            float4 q4=wq4[j];
            aqk[4*j+0]+=q4.x*xc; aqk[4*j+1]+=q4.y*xc; aqk[4*j+2]+=q4.z*xc; aqk[4*j+3]+=q4.w*xc;
        }
    }
    #pragma unroll
    for (int o=0;o<32;o++)
        g_Vh[((size_t)((b<<6)+half*32+o))*HWD + n] = __float2bfloat16(av[o]);
    const float f = half? 1.0f : (0.35355339059327373f * 1.4426950408889634f);
    unsigned* dst = half? g_Kh : g_Qh;
    #pragma unroll
    for (int dp=0;dp<4;dp++)
        dst[((b<<2)+dp)*HWD + n] = pack_bf16x2(aqk[2*dp+1]*f, aqk[2*dp]*f);
}

// ---------------- sobel / hsv / hist maps (gated per-sample) ----------------
__global__ void __launch_bounds__(128) spatial3_kernel(const float* __restrict__ x){
    const int b = blockIdx.y;
    if (g_branch[b] == 3) return;
    __shared__ float xs[2][4][64];
    const int y0 = blockIdx.x*2;
    const int t = threadIdx.x, ty = t>>6, tx = t&63;
    const int y = y0 + ty;
    const float* xb = x + ((size_t)b<<18);
    float ssum=0.f, csum=0.f, mx=-1e30f, mn=1e30f;
    #pragma unroll
    for (int i=t;i<256;i+=128){
        int r=i>>6, xx=i&63, yy=y0-1+r;
        xs[0][r][xx] = (yy>=0&&yy<64)? xb[(yy<<6)+xx] : 0.f;
    }
    __syncthreads();
    for (int c=0;c<64;c++){
        if (c+1<64){
            const float* xp = xb + ((size_t)(c+1)<<12);
            #pragma unroll
            for (int i=t;i<256;i+=128){
                int r=i>>6, xx=i&63, yy=y0-1+r;
                xs[(c+1)&1][r][xx] = (yy>=0&&yy<64)? xp[(yy<<6)+xx] : 0.f;
            }
        }
        const float (*cur)[64] = xs[c&1];
        float v[3][3];
        #pragma unroll
        for (int dy=0;dy<3;dy++)
            #pragma unroll
            for (int dx=-1;dx<=1;dx++){
                int xx=tx+dx;
                v[dy][dx+1] = (xx>=0&&xx<64)? cur[ty+dy][xx] : 0.f;
            }
        float gx = (v[0][2]+2.f*v[1][2]+v[2][2]) - (v[0][0]+2.f*v[1][0]+v[2][0]);
        float gy = (v[2][0]+2.f*v[2][1]+v[2][2]) - (v[0][0]+2.f*v[0][1]+v[0][2]);
        ssum += sqrtf(gx*gx+gy*gy);
        float ctr = v[1][1];
        csum += ctr; mx = fmaxf(mx,ctr); mn = fminf(mn,ctr);
        __syncthreads();
    }
    int id = (b<<12) + (y<<6) + tx;
    g_sobel[id] = sigmoidf_(ssum*(1.0f/64.0f));
    g_hsv[id]   = (mx-mn+1e-6f)/(mx+1e-6f);
    g_hist[id]  = sigmoidf_(csum*(1.0f/64.0f));
}

// ---------------- 64x64 DFT magnitude, gated per-sample on branch==3 ----------------
__global__ void fft_kernel(const float* __restrict__ x){
    const int c = blockIdx.x, b = blockIdx.y;
    if (g_branch[b] != 3) return;
    extern __shared__ float sm[];
    float* xs  = sm;
    float* re  = sm + 4096;
    float* im  = sm + 8192;
    float* twc = sm + 12288;
    float* tws = sm + 12352;
    const int t = threadIdx.x;
    const float* xp = x + ((size_t)(((b<<6)+c))<<12);
    for (int i=t;i<4096;i+=256) xs[i]=xp[i];
    if (t<64){ float s,co; sincosf(-6.283185307179586f * (float)t * (1.0f/64.0f), &s, &co); twc[t]=co; tws[t]=s; }
    __syncthreads();
    for (int o=t;o<4096;o+=256){
        int r=o>>6, v=o&63;
        const float* row = xs + (r<<6);
        float cr=0.f, ci=0.f;
        #pragma unroll 4
        for (int j=0;j<64;j++){
            int ti = (v*j)&63;
            float xv = row[j];
            cr += xv*twc[ti];
            ci += xv*tws[ti];
        }
        re[o]=cr; im[o]=ci;
    }
    __syncthreads();
    float* outp = g_fftmag + ((size_t)(((b<<6)+c))<<12);
    for (int o=t;o<4096;o+=256){
        int u=o>>6, v=o&63;
        float fr=0.f, fi=0.f;
        #pragma unroll 4
        for (int r=0;r<64;r++){
            int ti=(u*r)&63;
            float a = re[(r<<6)+v], bm = im[(r<<6)+v];
            float tc=twc[ti], ts=tws[ti];
            fr += a*tc - bm*ts;
            fi += a*ts + bm*tc;
        }
        float mag = sqrtf(fr*fr+fi*fi);
        int su=(u+32)&63, sv=(v+32)&63;
        outp[(su<<6)+sv]=mag;
    }
}

// ---------------- select map per sample, scale by spatial_weight ----------------
__global__ void combine_kernel(const float* __restrict__ swp){
    int id = blockIdx.x*256+threadIdx.x;
    int b = id>>12, p = id&4095;
    int br = g_branch[b];
    float v;
    if      (br==0) v = g_sobel[id];
    else if (br==1) v = g_hsv[id];
    else if (br==2) v = g_hist[id];
    else {
        float s=0.f;
        const float* mp = g_fftmag + ((size_t)b<<18) + p;
        #pragma unroll 4
        for (int c=0;c<64;c++) s += mp[(size_t)c<<12];
        v = sigmoidf_(s*(1.0f/64.0f));
    }
    g_spatial[id] = swp[0]*v;
}

// ---------------- tensor-core flash attention, split-KV x4 ----------------
// grid (64, NSPL, 4): x = 64-query tile, y = kv split, z = batch. 4 warps.
// Each split processes 8 kt tiles (1024 keys) and writes raw partial O + denom.
__global__ void __launch_bounds__(128) attention_kernel(){
    extern __shared__ char sm8[];
    unsigned* Ksu = (unsigned*)sm8;               // 4*136 u32 = 2176 B
    unsigned* Vsu = (unsigned*)(sm8 + 2176);      // 64*68 u32 = 17408 B
    float*    Osm = (float*)(sm8 + 2176);         // overlays Vsu
    const int t = threadIdx.x, lane = t&31, w = t>>5;
    const int g = lane>>2, l = lane&3;
    const int spl = blockIdx.y, b = blockIdx.z, n0 = blockIdx.x*64;
    const int qw = w*16;

    unsigned qa0 = g_Qh[((b<<2)+l)*HWD + n0 + qw + g];
    unsigned qa1 = g_Qh[((b<<2)+l)*HWD + n0 + qw + g + 8];
    const unsigned zz = 0u;

    float o[32];
    #pragma unroll
    for (int i=0;i<32;i++) o[i]=0.f;
    float d0=0.f, d1=0.f;

    const int kt0 = spl*(32/NSPL), kt1 = kt0 + (32/NSPL);
    for (int kt=kt0;kt<kt1;kt++){
        const int m0 = kt<<7;
        __syncthreads();
        {
            int dp = t>>5, j = t&31;
            ((uint4*)(Ksu + dp*136))[j] =
                ((const uint4*)(g_Kh + ((b<<2)+dp)*HWD + m0))[j];
        }
        for (int i=t;i<1024;i+=128){
            int r = i>>4, j = i&15;
            ((uint4*)(Vsu + r*68))[j] =
                ((const uint4*)(g_Vh + ((size_t)((b<<6)+r))*HWD + m0))[j];
        }
        __syncthreads();

        #pragma unroll 2
        for (int mc=0;mc<8;mc++){
            const int m16 = mc<<4;
            float s0,s1,s2,s3,s4,s5,s6,s7;
            unsigned kb0 = Ksu[l*136 + m16 + g];
            unsigned kb1 = Ksu[l*136 + m16 + 8 + g];
            asm("mma.sync.aligned.m16n8k16.row.col.f32.bf16.bf16.f32 "
                "{%0,%1,%2,%3},{%4,%5,%6,%7},{%8,%9},{%10,%11,%12,%13};"
                : "=f"(s0),"=f"(s1),"=f"(s2),"=f"(s3)
                : "r"(qa0),"r"(qa1),"r"(zz),"r"(zz), "r"(kb0),"r"(zz),
                  "f"(0.f),"f"(0.f),"f"(0.f),"f"(0.f));
            asm("mma.sync.aligned.m16n8k16.row.col.f32.bf16.bf16.f32 "
                "{%0,%1,%2,%3},{%4,%5,%6,%7},{%8,%9},{%10,%11,%12,%13};"
                : "=f"(s4),"=f"(s5),"=f"(s6),"=f"(s7)
                : "r"(qa0),"r"(qa1),"r"(zz),"r"(zz), "r"(kb1),"r"(zz),
                  "f"(0.f),"f"(0.f),"f"(0.f),"f"(0.f));
            s0=ex2_(s0); s1=ex2_(s1); s2=ex2_(s2); s3=ex2_(s3);
            s4=ex2_(s4); s5=ex2_(s5); s6=ex2_(s6); s7=ex2_(s7);
            d0 += (s0+s1)+(s4+s5);
            d1 += (s2+s3)+(s6+s7);
            unsigned p0 = pack_bf16x2(s1,s0);
            unsigned p1 = pack_bf16x2(s3,s2);
            unsigned p2 = pack_bf16x2(s5,s4);
            unsigned p3 = pack_bf16x2(s7,s6);
            const int vbase = (m16>>1) + l;
            #pragma unroll
            for (int ct=0;ct<8;ct++){
                unsigned vb0 = Vsu[(ct*8+g)*68 + vbase];
                unsigned vb1 = Vsu[(ct*8+g)*68 + vbase + 4];
                asm("mma.sync.aligned.m16n8k16.row.col.f32.bf16.bf16.f32 "
                    "{%0,%1,%2,%3},{%4,%5,%6,%7},{%8,%9},{%0,%1,%2,%3};"
                    : "+f"(o[ct*4+0]),"+f"(o[ct*4+1]),"+f"(o[ct*4+2]),"+f"(o[ct*4+3])
                    : "r"(p0),"r"(p1),"r"(p2),"r"(p3), "r"(vb0),"r"(vb1));
            }
        }
    }
    d0 += __shfl_xor_sync(0xffffffffu, d0, 1);
    d0 += __shfl_xor_sync(0xffffffffu, d0, 2);
    d1 += __shfl_xor_sync(0xffffffffu, d1, 1);
    d1 += __shfl_xor_sync(0xffffffffu, d1, 2);
    if (l == 0){
        g_dpart[((spl*BB + b)<<12) + n0 + qw + g    ] = d0;
        g_dpart[((spl*BB + b)<<12) + n0 + qw + g + 8] = d1;
    }

    __syncthreads();
    #pragma unroll
    for (int ct=0;ct<8;ct++){
        int c0 = ct*8 + 2*l;
        Osm[ c0   *68 + qw + g    ] = o[ct*4+0];
        Osm[(c0+1)*68 + qw + g    ] = o[ct*4+1];
        Osm[ c0   *68 + qw + g + 8] = o[ct*4+2];
        Osm[(c0+1)*68 + qw + g + 8] = o[ct*4+3];
    }
    __syncthreads();
    float* op = g_Opart + ((size_t)(spl*BB + b)*CC<<12) + n0;
    for (int i=t;i<4096;i+=128){
        int c = i>>6, q = i&63;
        op[((size_t)c<<12) + q] = Osm[c*68+q];
    }
}

// ---------------- combine split partials + routed epilogue ----------------
// grid (64, 4): block handles [b][all 64 c][n0..n0+63]
__global__ void __launch_bounds__(256) attn_finish(const float* __restrict__ x,
                                                   float* __restrict__ out){
    __shared__ float scl[64];
    const int t = threadIdx.x;
    const int b = blockIdx.y, n0 = blockIdx.x*64;
    if (t < 64){
        float d = 0.f;
        #pragma unroll
        for (int s=0;s<NSPL;s++) d += g_dpart[((s*BB + b)<<12) + n0 + t];
        scl[t] = g_spatial[(b<<12) + n0 + t] / d;
    }
    __syncthreads();
    for (int i=t;i<4096;i+=256){
        int c = i>>6, q = i&63;
        size_t po = ((size_t)(b*CC + c)<<12) + n0 + q;
        float osum = 0.f;
        #pragma unroll
        for (int s=0;s<NSPL;s++) osum += g_Opart[((size_t)(s*BB*CC)<<12) + po];
        size_t gi = ((size_t)(b*CC + c)<<12) + n0 + q;
        out[gi] = osum*scl[q] + x[gi];
    }
}

// ---------------- launch ----------------
extern "C" void kernel_launch(void* const* d_in, const int* in_sizes, int n_in,
                              void* d_out, int out_size){
    const float* x    = (const float*)d_in[0];
    const float* wq   = (const float*)d_in[1];
    const float* bq   = (const float*)d_in[2];
    const float* wk   = (const float*)d_in[3];
    const float* bk   = (const float*)d_in[4];
    const float* wv   = (const float*)d_in[5];
    const float* bv   = (const float*)d_in[6];
    const float* c1w  = (const float*)d_in[7];
    const float* c1b  = (const float*)d_in[8];
    const float* c2w  = (const float*)d_in[9];
    const float* c2b  = (const float*)d_in[10];
    const float* fcw  = (const float*)d_in[11];
    const float* fcb  = (const float*)d_in[12];
    const float* swp  = (const float*)d_in[13];
    float* out = (float*)d_out;

    cudaFuncSetAttribute(fft_kernel, cudaFuncAttributeMaxDynamicSharedMemorySize, 49664);

    conv1_kernel    <<<dim3(32,4), 256>>>(x, c1w, c1b);
    conv2_kernel    <<<dim3(128,4),256>>>(c2w, c2b);
    fc_argmax_kernel<<<1,128>>>(fcw, fcb);
    qkv_kernel      <<<dim3(64,4), 128>>>(x, wq,bq, wk,bk, wv,bv);
    spatial3_kernel <<<dim3(32,4), 128>>>(x);
    fft_kernel      <<<dim3(64,4), 256, 49664>>>(x);
    combine_kernel  <<<64,256>>>(swp);
    attention_kernel<<<dim3(64,NSPL,4), 128, 19584>>>();
    attn_finish     <<<dim3(64,4), 256>>>(x, out);
}

// round 5
// speedup vs baseline: 3.9863x; 1.3390x over previous
#include <cuda_runtime.h>
#include <cuda_bf16.h>

#define BB   4
#define CC   64
#define HWD  4096
#define QKD  8
#define NSPL 4

// ---------------- device scratch ----------------
__device__ unsigned       g_Qh[BB*4*HWD];   // bf16x2 pairs: [b][dpair][n], exp-scale folded in
__device__ unsigned       g_Kh[BB*4*HWD];   // bf16x2 pairs: [b][dpair][n]
__device__ __nv_bfloat16  g_Vh[BB*CC*HWD];  // [b][c][m]
__device__ float g_Opart[NSPL*BB*CC*HWD];   // split partial O
__device__ float g_dpart[NSPL*BB*HWD];      // split partial denom
__device__ float g_f1[BB*64*32*32];
__device__ float g_f2[BB*128];
__device__ int   g_branch[BB];
__device__ float g_sobel[BB*HWD];
__device__ float g_hsv[BB*HWD];
__device__ float g_hist[BB*HWD];
__device__ float g_fre[BB*CC*HWD];
__device__ float g_fim[BB*CC*HWD];
__device__ float g_fftmag[BB*CC*HWD];

__device__ const int c_branch_tab[25] =
    {0,0,0,0,0,0,1,1,0,0,0,0,0,0,3,1,1,2,3,0,0,3,3,3,3};

__device__ __forceinline__ float sigmoidf_(float z){ return 1.0f/(1.0f+__expf(-z)); }
__device__ __forceinline__ unsigned pack_bf16x2(float hi, float lo){
    unsigned r; asm("cvt.rn.bf16x2.f32 %0, %1, %2;" : "=r"(r) : "f"(hi), "f"(lo)); return r;
}
__device__ __forceinline__ float ex2_(float v){
    float r; asm("ex2.approx.f32 %0, %1;" : "=f"(r) : "f"(v)); return r;
}

// =====================================================================
// PHASE 1: conv1 (blocks 0..255)  ||  qkv (blocks 256..383).  256 thr.
// dyn smem: conv1 uses 13056 B, qkv uses 53248 B -> launch with 53248.
// =====================================================================
__global__ void __launch_bounds__(256) phase1_kernel(const float* __restrict__ x,
    const float* __restrict__ wq, const float* __restrict__ bq,
    const float* __restrict__ wk, const float* __restrict__ bk,
    const float* __restrict__ wv, const float* __restrict__ bv,
    const float* __restrict__ c1w, const float* __restrict__ c1b){
    extern __shared__ float smf[];
    const int blk = blockIdx.x, t = threadIdx.x;

    if (blk < 256){
        // ---- conv1: (b, ocg of 2 oc, y-half) -> relu -> g_f1[4,64,32,32]
        const int ocg = blk & 31, yh = (blk>>5)&1, b = blk>>6;
        float* xs = smf;           // 33*64 = 2112
        float* ws = smf + 2112;    // 2*64*9 = 1152
        for (int i=t;i<1152;i+=256) ws[i] = c1w[ocg*1152 + i];
        float acc[2][2] = {{0.f,0.f},{0.f,0.f}};
        const int px = t&31;
        const int ybase = yh*32 - 1;
        for (int ic=0; ic<64; ++ic){
            __syncthreads();
            const float* xp = x + (((size_t)b*64+ic)<<12);
            for (int i=t;i<2112;i+=256){
                int r=i>>6, xx=i&63, iy=ybase+r;
                xs[i] = (iy>=0 && iy<64) ? xp[(iy<<6)+xx] : 0.f;
            }
            __syncthreads();
            const float* wp0 = ws + ic*9;
            const float* wp1 = ws + 576 + ic*9;
            #pragma unroll
            for (int pi=0;pi<2;pi++){
                int py = (t>>5) + pi*8;
                int r0 = py*2, ix0 = px*2 - 1;
                float v[9];
                #pragma unroll
                for (int ky=0;ky<3;ky++)
                    #pragma unroll
                    for (int kx=0;kx<3;kx++){
                        int ix = ix0+kx;
                        v[ky*3+kx] = (ix>=0&&ix<64)? xs[(r0+ky)*64 + ix] : 0.f;
                    }
                float s0=0.f, s1=0.f;
                #pragma unroll
                for (int k=0;k<9;k++){ s0 += v[k]*wp0[k]; s1 += v[k]*wp1[k]; }
                acc[pi][0]+=s0; acc[pi][1]+=s1;
            }
        }
        #pragma unroll
        for (int ol=0;ol<2;ol++){
            int oc = ocg*2+ol;
            float bvl = c1b[oc];
            #pragma unroll
            for (int pi=0;pi<2;pi++){
                int oy = yh*16 + (t>>5) + pi*8;
                float v = acc[pi][ol]+bvl;
                g_f1[(((b*64)+oc)<<10) + (oy<<5) + px] = v>0.f? v : 0.f;
            }
        }
    } else {
        // ---- qkv: 128-n tiles, 2 halves x 128 n
        const int e = blk - 256;
        const int ntile = e & 31, b = e>>5;
        const int n0 = ntile*128;
        float* wqt = smf;            // 512
        float* wkt = smf + 512;      // 512
        float* wvt = smf + 1024;     // 4096
        float* xs  = smf + 5120;     // 8192 : [c][128]
        for (int i=t;i<512;i+=256){ int o=i>>6,c=i&63; wqt[c*8+o]=wq[i]; wkt[c*8+o]=wk[i]; }
        for (int i=t;i<4096;i+=256){ int o=i>>6,c=i&63; wvt[c*64+o]=wv[i]; }
        {
            const float* xb = x + (size_t)b*CC*HWD + n0;
            for (int i=t;i<8192;i+=256){ int c=i>>7, nl=i&127; xs[i] = xb[(size_t)c*HWD + nl]; }
        }
        __syncthreads();
        const int half = t>>7, nl = t&127;
        const int n = n0 + nl;
        float av[32], aqk[8];
        const float* bqk = half? bk : bq;
        #pragma unroll
        for (int o=0;o<32;o++) av[o]=bv[half*32+o];
        #pragma unroll
        for (int o=0;o<8;o++) aqk[o]=bqk[o];
        const float* wqkt = half? wkt : wqt;
        for (int c=0;c<64;c++){
            float xc = xs[(c<<7) + nl];
            const float4* wv4 = (const float4*)(wvt + c*64 + half*32);
            #pragma unroll
            for (int j=0;j<8;j++){
                float4 v = wv4[j];
                av[4*j+0]+=v.x*xc; av[4*j+1]+=v.y*xc; av[4*j+2]+=v.z*xc; av[4*j+3]+=v.w*xc;
            }
            const float4* wq4 = (const float4*)(wqkt + c*8);
            #pragma unroll
            for (int j=0;j<2;j++){
                float4 q4=wq4[j];
                aqk[4*j+0]+=q4.x*xc; aqk[4*j+1]+=q4.y*xc; aqk[4*j+2]+=q4.z*xc; aqk[4*j+3]+=q4.w*xc;
            }
        }
        #pragma unroll
        for (int o=0;o<32;o++)
            g_Vh[((size_t)((b<<6)+half*32+o))*HWD + n] = __float2bfloat16(av[o]);
        const float f = half? 1.0f : (0.35355339059327373f * 1.4426950408889634f);
        unsigned* dst = half? g_Kh : g_Qh;
        #pragma unroll
        for (int dp=0;dp<4;dp++)
            dst[((b<<2)+dp)*HWD + n] = pack_bf16x2(aqk[2*dp+1]*f, aqk[2*dp]*f);
    }
}

// =====================================================================
// PHASE 2: attention (blocks 0..1023) || conv2 (1024..1535) || spatial3
// (1536..1663).  128 thr.  dyn smem 19584 B.
// =====================================================================
__global__ void __launch_bounds__(128) phase2_kernel(const float* __restrict__ x,
    const float* __restrict__ c2w, const float* __restrict__ c2b){
    extern __shared__ char sm8[];
    const int blk = blockIdx.x, t = threadIdx.x;

    if (blk < 1024){
        // ---- tensor-core flash attention, split-KV x4
        unsigned* Ksu = (unsigned*)sm8;               // 4*136 u32
        unsigned* Vsu = (unsigned*)(sm8 + 2176);      // 64*68 u32
        float*    Osm = (float*)(sm8 + 2176);         // overlays Vsu
        const int lane = t&31, w = t>>5;
        const int g = lane>>2, l = lane&3;
        const int qt = blk & 63, spl = (blk>>6)&3, b = blk>>8;
        const int n0 = qt*64;
        const int qw = w*16;

        unsigned qa0 = g_Qh[((b<<2)+l)*HWD + n0 + qw + g];
        unsigned qa1 = g_Qh[((b<<2)+l)*HWD + n0 + qw + g + 8];
        const unsigned zz = 0u;

        float o[32];
        #pragma unroll
        for (int i=0;i<32;i++) o[i]=0.f;
        float d0=0.f, d1=0.f;

        const int kt0 = spl*(32/NSPL), kt1 = kt0 + (32/NSPL);
        for (int kt=kt0;kt<kt1;kt++){
            const int m0 = kt<<7;
            __syncthreads();
            {
                int dp = t>>5, j = t&31;
                ((uint4*)(Ksu + dp*136))[j] =
                    ((const uint4*)(g_Kh + ((b<<2)+dp)*HWD + m0))[j];
            }
            for (int i=t;i<1024;i+=128){
                int r = i>>4, j = i&15;
                ((uint4*)(Vsu + r*68))[j] =
                    ((const uint4*)(g_Vh + ((size_t)((b<<6)+r))*HWD + m0))[j];
            }
            __syncthreads();

            #pragma unroll 2
            for (int mc=0;mc<8;mc++){
                const int m16 = mc<<4;
                float s0,s1,s2,s3,s4,s5,s6,s7;
                unsigned kb0 = Ksu[l*136 + m16 + g];
                unsigned kb1 = Ksu[l*136 + m16 + 8 + g];
                asm("mma.sync.aligned.m16n8k16.row.col.f32.bf16.bf16.f32 "
                    "{%0,%1,%2,%3},{%4,%5,%6,%7},{%8,%9},{%10,%11,%12,%13};"
                    : "=f"(s0),"=f"(s1),"=f"(s2),"=f"(s3)
                    : "r"(qa0),"r"(qa1),"r"(zz),"r"(zz), "r"(kb0),"r"(zz),
                      "f"(0.f),"f"(0.f),"f"(0.f),"f"(0.f));
                asm("mma.sync.aligned.m16n8k16.row.col.f32.bf16.bf16.f32 "
                    "{%0,%1,%2,%3},{%4,%5,%6,%7},{%8,%9},{%10,%11,%12,%13};"
                    : "=f"(s4),"=f"(s5),"=f"(s6),"=f"(s7)
                    : "r"(qa0),"r"(qa1),"r"(zz),"r"(zz), "r"(kb1),"r"(zz),
                      "f"(0.f),"f"(0.f),"f"(0.f),"f"(0.f));
                s0=ex2_(s0); s1=ex2_(s1); s2=ex2_(s2); s3=ex2_(s3);
                s4=ex2_(s4); s5=ex2_(s5); s6=ex2_(s6); s7=ex2_(s7);
                d0 += (s0+s1)+(s4+s5);
                d1 += (s2+s3)+(s6+s7);
                unsigned p0 = pack_bf16x2(s1,s0);
                unsigned p1 = pack_bf16x2(s3,s2);
                unsigned p2 = pack_bf16x2(s5,s4);
                unsigned p3 = pack_bf16x2(s7,s6);
                const int vbase = (m16>>1) + l;
                #pragma unroll
                for (int ct=0;ct<8;ct++){
                    unsigned vb0 = Vsu[(ct*8+g)*68 + vbase];
                    unsigned vb1 = Vsu[(ct*8+g)*68 + vbase + 4];
                    asm("mma.sync.aligned.m16n8k16.row.col.f32.bf16.bf16.f32 "
                        "{%0,%1,%2,%3},{%4,%5,%6,%7},{%8,%9},{%0,%1,%2,%3};"
                        : "+f"(o[ct*4+0]),"+f"(o[ct*4+1]),"+f"(o[ct*4+2]),"+f"(o[ct*4+3])
                        : "r"(p0),"r"(p1),"r"(p2),"r"(p3), "r"(vb0),"r"(vb1));
                }
            }
        }
        d0 += __shfl_xor_sync(0xffffffffu, d0, 1);
        d0 += __shfl_xor_sync(0xffffffffu, d0, 2);
        d1 += __shfl_xor_sync(0xffffffffu, d1, 1);
        d1 += __shfl_xor_sync(0xffffffffu, d1, 2);
        if (l == 0){
            g_dpart[((spl*BB + b)<<12) + n0 + qw + g    ] = d0;
            g_dpart[((spl*BB + b)<<12) + n0 + qw + g + 8] = d1;
        }

        __syncthreads();
        #pragma unroll
        for (int ct=0;ct<8;ct++){
            int c0 = ct*8 + 2*l;
            Osm[ c0   *68 + qw + g    ] = o[ct*4+0];
            Osm[(c0+1)*68 + qw + g    ] = o[ct*4+1];
            Osm[ c0   *68 + qw + g + 8] = o[ct*4+2];
            Osm[(c0+1)*68 + qw + g + 8] = o[ct*4+3];
        }
        __syncthreads();
        float* op = g_Opart + ((size_t)(spl*BB + b)*CC<<12) + n0;
        for (int i=t;i<4096;i+=128){
            int c = i>>6, q = i&63;
            op[((size_t)c<<12) + q] = Osm[c*68+q];
        }
    } else if (blk < 1536){
        // ---- conv2 + relu + spatial mean -> g_f2[4,128]   (128 thr, 2 px)
        float* smf = (float*)sm8;
        float* xs  = smf;          // 1024
        float* ws  = smf + 1024;   // 576
        float* red = smf + 1600;   // 128
        const int e = blk - 1024;
        const int oc = e & 127, b = e>>7;
        for (int i=t;i<576;i+=128) ws[i]=c2w[oc*576+i];
        float acc0=0.f, acc1=0.f;
        const int ox = t&15;
        for (int ic=0;ic<64;++ic){
            __syncthreads();
            const float* xp = g_f1 + (((b*64)+ic)<<10);
            for (int i=t;i<1024;i+=128) xs[i]=xp[i];
            __syncthreads();
            const float* wp = ws + ic*9;
            #pragma unroll
            for (int pi=0;pi<2;pi++){
                int oy = (t>>4) + pi*8;
                int iy0=2*oy-1, ix0=2*ox-1;
                float a=0.f;
                #pragma unroll
                for (int ky=0;ky<3;ky++)
                    #pragma unroll
                    for (int kx=0;kx<3;kx++){
                        int iy=iy0+ky, ix=ix0+kx;
                        float xv = (iy>=0&&iy<32&&ix>=0&&ix<32)? xs[(iy<<5)+ix] : 0.0f;
                        a += xv*wp[ky*3+kx];
                    }
                if (pi==0) acc0+=a; else acc1+=a;
            }
        }
        float bvl = c2b[oc];
        float r0 = acc0+bvl; r0 = r0>0.f? r0:0.f;
        float r1 = acc1+bvl; r1 = r1>0.f? r1:0.f;
        red[t]=r0+r1; __syncthreads();
        for (int s=64;s>0;s>>=1){ if(t<s) red[t]+=red[t+s]; __syncthreads(); }
        if (t==0) g_f2[b*128+oc] = red[0]*(1.0f/256.0f);
    } else {
        // ---- sobel/hsv/hist maps (ungated), 2 rows per block
        float (*xs)[4][64] = (float (*)[4][64])sm8;   // [2][4][64]
        const int e = blk - 1536;
        const int seg = e & 31, b = e>>5;
        const int y0 = seg*2;
        const int ty = t>>6, tx = t&63;
        const int y = y0 + ty;
        const float* xb = x + ((size_t)b<<18);
        float ssum=0.f, csum=0.f, mx=-1e30f, mn=1e30f;
        #pragma unroll
        for (int i=t;i<256;i+=128){
            int r=i>>6, xx=i&63, yy=y0-1+r;
            xs[0][r][xx] = (yy>=0&&yy<64)? xb[(yy<<6)+xx] : 0.f;
        }
        __syncthreads();
        for (int c=0;c<64;c++){
            if (c+1<64){
                const float* xp = xb + ((size_t)(c+1)<<12);
                #pragma unroll
                for (int i=t;i<256;i+=128){
                    int r=i>>6, xx=i&63, yy=y0-1+r;
                    xs[(c+1)&1][r][xx] = (yy>=0&&yy<64)? xp[(yy<<6)+xx] : 0.f;
                }
            }
            const float (*cur)[64] = xs[c&1];
            float v[3][3];
            #pragma unroll
            for (int dy=0;dy<3;dy++)
                #pragma unroll
                for (int dx=-1;dx<=1;dx++){
                    int xx=tx+dx;
                    v[dy][dx+1] = (xx>=0&&xx<64)? cur[ty+dy][xx] : 0.f;
                }
            float gx = (v[0][2]+2.f*v[1][2]+v[2][2]) - (v[0][0]+2.f*v[1][0]+v[2][0]);
            float gy = (v[2][0]+2.f*v[2][1]+v[2][2]) - (v[0][0]+2.f*v[0][1]+v[0][2]);
            ssum += sqrtf(gx*gx+gy*gy);
            float ctr = v[1][1];
            csum += ctr; mx = fmaxf(mx,ctr); mn = fminf(mn,ctr);
            __syncthreads();
        }
        int id = (b<<12) + (y<<6) + tx;
        g_sobel[id] = sigmoidf_(ssum*(1.0f/64.0f));
        g_hsv[id]   = (mx-mn+1e-6f)/(mx+1e-6f);
        g_hist[id]  = sigmoidf_(csum*(1.0f/64.0f));
    }
}

// ---------------- fc + argmax ----------------
__global__ void fc_argmax_kernel(const float* __restrict__ fcw,
                                 const float* __restrict__ fcb){
    int wid = threadIdx.x>>5, lane = threadIdx.x&31;
    if (wid >= BB) return;
    float v = -1e30f; int idx = lane;
    if (lane < 25){
        float s = fcb[lane];
        const float* f2   = g_f2 + wid*128;
        const float* wrow = fcw  + lane*128;
        #pragma unroll 4
        for (int k=0;k<128;k++) s += f2[k]*wrow[k];
        v = s;
    }
    #pragma unroll
    for (int off=16;off>0;off>>=1){
        float ov = __shfl_down_sync(0xffffffffu, v,   off);
        int   oi = __shfl_down_sync(0xffffffffu, idx, off);
        if (ov > v || (ov==v && oi<idx)){ v=ov; idx=oi; }
    }
    if (lane==0) g_branch[wid] = c_branch_tab[idx];
}

// ---------------- fftA: row DFT (gated), grid (256, 4), 256 thr ----------------
__global__ void __launch_bounds__(256) fftA_kernel(const float* __restrict__ x){
    const int b = blockIdx.y;
    if (g_branch[b] != 3) return;
    const int e = blockIdx.x;
    const int c = e>>2, qr = e&3;       // quarter of rows
    __shared__ float xs[16*64];
    __shared__ float twc[64], tws[64];
    const int t = threadIdx.x;
    if (t<64){ float s,co; sincosf(-6.283185307179586f*(float)t*(1.0f/64.0f), &s,&co); twc[t]=co; tws[t]=s; }
    const float* xp = x + ((size_t)(((b<<6)+c))<<12) + (qr<<10);
    for (int i=t;i<1024;i+=256) xs[i]=xp[i];
    __syncthreads();
    float* fre = g_fre + ((size_t)(((b<<6)+c))<<12) + (qr<<10);
    float* fim = g_fim + ((size_t)(((b<<6)+c))<<12) + (qr<<10);
    #pragma unroll
    for (int k=0;k<4;k++){
        int o = t + k*256;
        int lr = o>>6, v = o&63;
        const float* row = xs + (lr<<6);
        float cr=0.f, ci=0.f;
        #pragma unroll 4
        for (int j=0;j<64;j++){
            int ti = (v*j)&63;
            float xv = row[j];
            cr += xv*twc[ti];
            ci += xv*tws[ti];
        }
        fre[o]=cr; fim[o]=ci;
    }
}

// ---------------- fftB: col DFT + mag + shift (gated), grid (256, 4) ----------------
__global__ void __launch_bounds__(256) fftB_kernel(){
    const int b = blockIdx.y;
    if (g_branch[b] != 3) return;
    const int e = blockIdx.x;
    const int c = e>>2, uq = e&3;       // quarter of u range
    __shared__ float re[4096], im[4096];
    __shared__ float twc[64], tws[64];
    const int t = threadIdx.x;
    if (t<64){ float s,co; sincosf(-6.283185307179586f*(float)t*(1.0f/64.0f), &s,&co); twc[t]=co; tws[t]=s; }
    const float* fre = g_fre + ((size_t)(((b<<6)+c))<<12);
    const float* fim = g_fim + ((size_t)(((b<<6)+c))<<12);
    for (int i=t;i<4096;i+=256){ re[i]=fre[i]; im[i]=fim[i]; }
    __syncthreads();
    float* outp = g_fftmag + ((size_t)(((b<<6)+c))<<12);
    #pragma unroll
    for (int k=0;k<4;k++){
        int o = t + k*256;
        int u = (uq<<4) + (o>>6), v = o&63;
        float fr=0.f, fi=0.f;
        #pragma unroll 4
        for (int r=0;r<64;r++){
            int ti=(u*r)&63;
            float a = re[(r<<6)+v], bm = im[(r<<6)+v];
            float tc=twc[ti], ts=tws[ti];
            fr += a*tc - bm*ts;
            fi += a*ts + bm*tc;
        }
        float mag = sqrtf(fr*fr+fi*fi);
        int su=(u+32)&63, sv=(v+32)&63;
        outp[(su<<6)+sv]=mag;
    }
}

// ---------------- combine split partials + routed spatial epilogue ----------------
__global__ void __launch_bounds__(256) attn_finish(const float* __restrict__ x,
                                                   const float* __restrict__ swp,
                                                   float* __restrict__ out){
    __shared__ float scl[64];
    const int t = threadIdx.x;
    const int b = blockIdx.y, n0 = blockIdx.x*64;
    if (t < 64){
        float d = 0.f;
        #pragma unroll
        for (int s=0;s<NSPL;s++) d += g_dpart[((s*BB + b)<<12) + n0 + t];
        const int br = g_branch[b];
        const int id = (b<<12) + n0 + t;
        float v;
        if      (br==0) v = g_sobel[id];
        else if (br==1) v = g_hsv[id];
        else if (br==2) v = g_hist[id];
        else {
            float s=0.f;
            const float* mp = g_fftmag + ((size_t)b<<18) + n0 + t;
            #pragma unroll 4
            for (int c=0;c<64;c++) s += mp[(size_t)c<<12];
            v = sigmoidf_(s*(1.0f/64.0f));
        }
        scl[t] = swp[0]*v/d;
    }
    __syncthreads();
    for (int i=t;i<4096;i+=256){
        int c = i>>6, q = i&63;
        size_t po = ((size_t)(b*CC + c)<<12) + n0 + q;
        float osum = 0.f;
        #pragma unroll
        for (int s=0;s<NSPL;s++) osum += g_Opart[((size_t)(s*BB*CC)<<12) + po];
        out[po] = osum*scl[q] + x[po];
    }
}

// ---------------- launch ----------------
extern "C" void kernel_launch(void* const* d_in, const int* in_sizes, int n_in,
                              void* d_out, int out_size){
    const float* x    = (const float*)d_in[0];
    const float* wq   = (const float*)d_in[1];
    const float* bq   = (const float*)d_in[2];
    const float* wk   = (const float*)d_in[3];
    const float* bk   = (const float*)d_in[4];
    const float* wv   = (const float*)d_in[5];
    const float* bv   = (const float*)d_in[6];
    const float* c1w  = (const float*)d_in[7];
    const float* c1b  = (const float*)d_in[8];
    const float* c2w  = (const float*)d_in[9];
    const float* c2b  = (const float*)d_in[10];
    const float* fcw  = (const float*)d_in[11];
    const float* fcb  = (const float*)d_in[12];
    const float* swp  = (const float*)d_in[13];
    float* out = (float*)d_out;

    cudaFuncSetAttribute(phase1_kernel, cudaFuncAttributeMaxDynamicSharedMemorySize, 53248);

    phase1_kernel  <<<384, 256, 53248>>>(x, wq,bq, wk,bk, wv,bv, c1w, c1b);
    phase2_kernel  <<<1664, 128, 19584>>>(x, c2w, c2b);
    fc_argmax_kernel<<<1,128>>>(fcw, fcb);
    fftA_kernel    <<<dim3(256,4), 256>>>(x);
    fftB_kernel    <<<dim3(256,4), 256>>>();
    attn_finish    <<<dim3(64,4), 256>>>(x, swp, out);
}

// round 7
// speedup vs baseline: 4.4409x; 1.1140x over previous
#include <cuda_runtime.h>
#include <cuda_bf16.h>

#define BB   4
#define CC   64
#define HWD  4096
#define QKD  8
#define NSPL 4
#define NV   33   // Hermitian: v = 0..32

// ---------------- device scratch ----------------
__device__ unsigned       g_Qh[BB*4*HWD];
__device__ unsigned       g_Kh[BB*4*HWD];
__device__ __nv_bfloat16  g_Vh[BB*CC*HWD];
__device__ float g_Opart[NSPL*BB*CC*HWD];
__device__ float g_dpart[NSPL*BB*HWD];
__device__ float g_f1[BB*64*32*32];
__device__ float g_f2[BB*128];
__device__ int   g_branch[BB];
__device__ float g_sobel[BB*HWD];
__device__ float g_hsv[BB*HWD];
__device__ float g_hist[BB*HWD];
__device__ float g_fre[BB*CC*NV*64];   // [b][c][v][r]
__device__ float g_fim[BB*CC*NV*64];
__device__ float g_fftmag[BB*CC*HWD];

__device__ const int c_branch_tab[25] =
    {0,0,0,0,0,0,1,1,0,0,0,0,0,0,3,1,1,2,3,0,0,3,3,3,3};

__device__ __forceinline__ float sigmoidf_(float z){ return 1.0f/(1.0f+__expf(-z)); }
__device__ __forceinline__ unsigned pack_bf16x2(float hi, float lo){
    unsigned r; asm("cvt.rn.bf16x2.f32 %0, %1, %2;" : "=r"(r) : "f"(hi), "f"(lo)); return r;
}
__device__ __forceinline__ float ex2_(float v){
    float r; asm("ex2.approx.f32 %0, %1;" : "=f"(r) : "f"(v)); return r;
}

// =====================================================================
// PHASE 1: conv1 (blocks 0..255) || qkv (blocks 256..511). 256 thr.
// dyn smem: conv1 13056 B, qkv 36864 B -> launch 36864.
// =====================================================================
__global__ void __launch_bounds__(256) phase1_kernel(const float* __restrict__ x,
    const float* __restrict__ wq, const float* __restrict__ bq,
    const float* __restrict__ wk, const float* __restrict__ bk,
    const float* __restrict__ wv, const float* __restrict__ bv,
    const float* __restrict__ c1w, const float* __restrict__ c1b){
    extern __shared__ float smf[];
    const int blk = blockIdx.x, t = threadIdx.x;

    if (blk < 256){
        // ---- conv1: (b, ocg of 2 oc, y-half) -> relu -> g_f1[4,64,32,32]
        const int ocg = blk & 31, yh = (blk>>5)&1, b = blk>>6;
        float* xs = smf;           // 33*64 = 2112
        float* ws = smf + 2112;    // 1152
        for (int i=t;i<1152;i+=256) ws[i] = c1w[ocg*1152 + i];
        float acc[2][2] = {{0.f,0.f},{0.f,0.f}};
        const int px = t&31;
        const int ybase = yh*32 - 1;
        for (int ic=0; ic<64; ++ic){
            __syncthreads();
            const float* xp = x + (((size_t)b*64+ic)<<12);
            for (int i=t;i<2112;i+=256){
                int r=i>>6, xx=i&63, iy=ybase+r;
                xs[i] = (iy>=0 && iy<64) ? xp[(iy<<6)+xx] : 0.f;
            }
            __syncthreads();
            const float* wp0 = ws + ic*9;
            const float* wp1 = ws + 576 + ic*9;
            #pragma unroll
            for (int pi=0;pi<2;pi++){
                int py = (t>>5) + pi*8;
                int r0 = py*2, ix0 = px*2 - 1;
                float v[9];
                #pragma unroll
                for (int ky=0;ky<3;ky++)
                    #pragma unroll
                    for (int kx=0;kx<3;kx++){
                        int ix = ix0+kx;
                        v[ky*3+kx] = (ix>=0&&ix<64)? xs[(r0+ky)*64 + ix] : 0.f;
                    }
                float s0=0.f, s1=0.f;
                #pragma unroll
                for (int k=0;k<9;k++){ s0 += v[k]*wp0[k]; s1 += v[k]*wp1[k]; }
                acc[pi][0]+=s0; acc[pi][1]+=s1;
            }
        }
        #pragma unroll
        for (int ol=0;ol<2;ol++){
            int oc = ocg*2+ol;
            float bvl = c1b[oc];
            #pragma unroll
            for (int pi=0;pi<2;pi++){
                int oy = yh*16 + (t>>5) + pi*8;
                float v = acc[pi][ol]+bvl;
                g_f1[(((b*64)+oc)<<10) + (oy<<5) + px] = v>0.f? v : 0.f;
            }
        }
    } else {
        // ---- qkv: 64-n tiles, 4 thread-quarters (16 V ch each; q0 adds Q, q1 adds K)
        const int e = blk - 256;
        const int ntile = e & 63, b = e>>6;
        const int n0 = ntile*64;
        float* wqt = smf;            // 512
        float* wkt = smf + 512;      // 512
        float* wvt = smf + 1024;     // 4096
        float* xs  = smf + 5120;     // 4096 : [c][64]
        for (int i=t;i<512;i+=256){ int o=i>>6,c=i&63; wqt[c*8+o]=wq[i]; wkt[c*8+o]=wk[i]; }
        for (int i=t;i<4096;i+=256){ int o=i>>6,c=i&63; wvt[c*64+o]=wv[i]; }
        {
            const float* xb = x + (size_t)b*CC*HWD + n0;
            for (int i=t;i<4096;i+=256){ int c=i>>6, nl=i&63; xs[i] = xb[(size_t)c*HWD + nl]; }
        }
        __syncthreads();
        const int qt = t>>6, nl = t&63;
        const int n = n0 + nl;
        float av[16], aqk[8];
        #pragma unroll
        for (int o=0;o<16;o++) av[o]=bv[qt*16+o];
        const float* bqk = (qt==1)? bk : bq;
        #pragma unroll
        for (int o=0;o<8;o++) aqk[o]=bqk[o];
        const float* wqkt = (qt==1)? wkt : wqt;
        for (int c=0;c<64;c++){
            float xc = xs[(c<<6) + nl];
            const float4* wv4 = (const float4*)(wvt + c*64 + qt*16);
            #pragma unroll
            for (int j=0;j<4;j++){
                float4 v = wv4[j];
                av[4*j+0]+=v.x*xc; av[4*j+1]+=v.y*xc; av[4*j+2]+=v.z*xc; av[4*j+3]+=v.w*xc;
            }
            if (qt < 2){
                const float4* wq4 = (const float4*)(wqkt + c*8);
                #pragma unroll
                for (int j=0;j<2;j++){
                    float4 q4=wq4[j];
                    aqk[4*j+0]+=q4.x*xc; aqk[4*j+1]+=q4.y*xc; aqk[4*j+2]+=q4.z*xc; aqk[4*j+3]+=q4.w*xc;
                }
            }
        }
        #pragma unroll
        for (int o=0;o<16;o++)
            g_Vh[((size_t)((b<<6)+qt*16+o))*HWD + n] = __float2bfloat16(av[o]);
        if (qt < 2){
            const float f = (qt==1)? 1.0f : (0.35355339059327373f * 1.4426950408889634f);
            unsigned* dst = (qt==1)? g_Kh : g_Qh;
            #pragma unroll
            for (int dp=0;dp<4;dp++)
                dst[((b<<2)+dp)*HWD + n] = pack_bf16x2(aqk[2*dp+1]*f, aqk[2*dp]*f);
        }
    }
}

// =====================================================================
// PHASE 2: attention (0..1023) || conv2 (1024..1535) || spatial3
// (1536..1663) || fftA row-DFT ungated (1664..2175). 128 thr, 19584 B.
// =====================================================================
__global__ void __launch_bounds__(128) phase2_kernel(const float* __restrict__ x,
    const float* __restrict__ c2w, const float* __restrict__ c2b){
    extern __shared__ char sm8[];
    const int blk = blockIdx.x, t = threadIdx.x;

    if (blk < 1024){
        // ---- tensor-core flash attention, split-KV x4
        unsigned* Ksu = (unsigned*)sm8;               // 4*136 u32
        unsigned* Vsu = (unsigned*)(sm8 + 2176);      // 64*68 u32
        float*    Osm = (float*)(sm8 + 2176);
        const int lane = t&31, w = t>>5;
        const int g = lane>>2, l = lane&3;
        const int qt = blk & 63, spl = (blk>>6)&3, b = blk>>8;
        const int n0 = qt*64;
        const int qw = w*16;

        unsigned qa0 = g_Qh[((b<<2)+l)*HWD + n0 + qw + g];
        unsigned qa1 = g_Qh[((b<<2)+l)*HWD + n0 + qw + g + 8];
        const unsigned zz = 0u;

        float o[32];
        #pragma unroll
        for (int i=0;i<32;i++) o[i]=0.f;
        float d0=0.f, d1=0.f;

        const int kt0 = spl*(32/NSPL), kt1 = kt0 + (32/NSPL);
        for (int kt=kt0;kt<kt1;kt++){
            const int m0 = kt<<7;
            __syncthreads();
            {
                int dp = t>>5, j = t&31;
                ((uint4*)(Ksu + dp*136))[j] =
                    ((const uint4*)(g_Kh + ((b<<2)+dp)*HWD + m0))[j];
            }
            for (int i=t;i<1024;i+=128){
                int r = i>>4, j = i&15;
                ((uint4*)(Vsu + r*68))[j] =
                    ((const uint4*)(g_Vh + ((size_t)((b<<6)+r))*HWD + m0))[j];
            }
            __syncthreads();

            #pragma unroll 2
            for (int mc=0;mc<8;mc++){
                const int m16 = mc<<4;
                float s0,s1,s2,s3,s4,s5,s6,s7;
                unsigned kb0 = Ksu[l*136 + m16 + g];
                unsigned kb1 = Ksu[l*136 + m16 + 8 + g];
                asm("mma.sync.aligned.m16n8k16.row.col.f32.bf16.bf16.f32 "
                    "{%0,%1,%2,%3},{%4,%5,%6,%7},{%8,%9},{%10,%11,%12,%13};"
                    : "=f"(s0),"=f"(s1),"=f"(s2),"=f"(s3)
                    : "r"(qa0),"r"(qa1),"r"(zz),"r"(zz), "r"(kb0),"r"(zz),
                      "f"(0.f),"f"(0.f),"f"(0.f),"f"(0.f));
                asm("mma.sync.aligned.m16n8k16.row.col.f32.bf16.bf16.f32 "
                    "{%0,%1,%2,%3},{%4,%5,%6,%7},{%8,%9},{%10,%11,%12,%13};"
                    : "=f"(s4),"=f"(s5),"=f"(s6),"=f"(s7)
                    : "r"(qa0),"r"(qa1),"r"(zz),"r"(zz), "r"(kb1),"r"(zz),
                      "f"(0.f),"f"(0.f),"f"(0.f),"f"(0.f));
                s0=ex2_(s0); s1=ex2_(s1); s2=ex2_(s2); s3=ex2_(s3);
                s4=ex2_(s4); s5=ex2_(s5); s6=ex2_(s6); s7=ex2_(s7);
                d0 += (s0+s1)+(s4+s5);
                d1 += (s2+s3)+(s6+s7);
                unsigned p0 = pack_bf16x2(s1,s0);
                unsigned p1 = pack_bf16x2(s3,s2);
                unsigned p2 = pack_bf16x2(s5,s4);
                unsigned p3 = pack_bf16x2(s7,s6);
                const int vbase = (m16>>1) + l;
                #pragma unroll
                for (int ct=0;ct<8;ct++){
                    unsigned vb0 = Vsu[(ct*8+g)*68 + vbase];
                    unsigned vb1 = Vsu[(ct*8+g)*68 + vbase + 4];
                    asm("mma.sync.aligned.m16n8k16.row.col.f32.bf16.bf16.f32 "
                        "{%0,%1,%2,%3},{%4,%5,%6,%7},{%8,%9},{%0,%1,%2,%3};"
                        : "+f"(o[ct*4+0]),"+f"(o[ct*4+1]),"+f"(o[ct*4+2]),"+f"(o[ct*4+3])
                        : "r"(p0),"r"(p1),"r"(p2),"r"(p3), "r"(vb0),"r"(vb1));
                }
            }
        }
        d0 += __shfl_xor_sync(0xffffffffu, d0, 1);
        d0 += __shfl_xor_sync(0xffffffffu, d0, 2);
        d1 += __shfl_xor_sync(0xffffffffu, d1, 1);
        d1 += __shfl_xor_sync(0xffffffffu, d1, 2);
        if (l == 0){
            g_dpart[((spl*BB + b)<<12) + n0 + qw + g    ] = d0;
            g_dpart[((spl*BB + b)<<12) + n0 + qw + g + 8] = d1;
        }

        __syncthreads();
        #pragma unroll
        for (int ct=0;ct<8;ct++){
            int c0 = ct*8 + 2*l;
            Osm[ c0   *68 + qw + g    ] = o[ct*4+0];
            Osm[(c0+1)*68 + qw + g    ] = o[ct*4+1];
            Osm[ c0   *68 + qw + g + 8] = o[ct*4+2];
            Osm[(c0+1)*68 + qw + g + 8] = o[ct*4+3];
        }
        __syncthreads();
        float* op = g_Opart + ((size_t)(spl*BB + b)*CC<<12) + n0;
        for (int i=t;i<4096;i+=128){
            int c = i>>6, q = i&63;
            op[((size_t)c<<12) + q] = Osm[c*68+q];
        }
    } else if (blk < 1536){
        // ---- conv2 + relu + spatial mean -> g_f2[4,128]
        float* smf = (float*)sm8;
        float* xs  = smf;          // 1024
        float* ws  = smf + 1024;   // 576
        float* red = smf + 1600;   // 128
        const int e = blk - 1024;
        const int oc = e & 127, b = e>>7;
        for (int i=t;i<576;i+=128) ws[i]=c2w[oc*576+i];
        float acc0=0.f, acc1=0.f;
        const int ox = t&15;
        for (int ic=0;ic<64;++ic){
            __syncthreads();
            const float* xp = g_f1 + (((b*64)+ic)<<10);
            for (int i=t;i<1024;i+=128) xs[i]=xp[i];
            __syncthreads();
            const float* wp = ws + ic*9;
            #pragma unroll
            for (int pi=0;pi<2;pi++){
                int oy = (t>>4) + pi*8;
                int iy0=2*oy-1, ix0=2*ox-1;
                float a=0.f;
                #pragma unroll
                for (int ky=0;ky<3;ky++)
                    #pragma unroll
                    for (int kx=0;kx<3;kx++){
                        int iy=iy0+ky, ix=ix0+kx;
                        float xv = (iy>=0&&iy<32&&ix>=0&&ix<32)? xs[(iy<<5)+ix] : 0.0f;
                        a += xv*wp[ky*3+kx];
                    }
                if (pi==0) acc0+=a; else acc1+=a;
            }
        }
        float bvl = c2b[oc];
        float r0 = acc0+bvl; r0 = r0>0.f? r0:0.f;
        float r1 = acc1+bvl; r1 = r1>0.f? r1:0.f;
        red[t]=r0+r1; __syncthreads();
        for (int s=64;s>0;s>>=1){ if(t<s) red[t]+=red[t+s]; __syncthreads(); }
        if (t==0) g_f2[b*128+oc] = red[0]*(1.0f/256.0f);
    } else if (blk < 1664){
        // ---- sobel/hsv/hist maps (ungated), 2 rows per block
        float (*xs)[4][64] = (float (*)[4][64])sm8;
        const int e = blk - 1536;
        const int seg = e & 31, b = e>>5;
        const int y0 = seg*2;
        const int ty = t>>6, tx = t&63;
        const int y = y0 + ty;
        const float* xb = x + ((size_t)b<<18);
        float ssum=0.f, csum=0.f, mx=-1e30f, mn=1e30f;
        #pragma unroll
        for (int i=t;i<256;i+=128){
            int r=i>>6, xx=i&63, yy=y0-1+r;
            xs[0][r][xx] = (yy>=0&&yy<64)? xb[(yy<<6)+xx] : 0.f;
        }
        __syncthreads();
        for (int c=0;c<64;c++){
            if (c+1<64){
                const float* xp = xb + ((size_t)(c+1)<<12);
                #pragma unroll
                for (int i=t;i<256;i+=128){
                    int r=i>>6, xx=i&63, yy=y0-1+r;
                    xs[(c+1)&1][r][xx] = (yy>=0&&yy<64)? xp[(yy<<6)+xx] : 0.f;
                }
            }
            const float (*cur)[64] = xs[c&1];
            float v[3][3];
            #pragma unroll
            for (int dy=0;dy<3;dy++)
                #pragma unroll
                for (int dx=-1;dx<=1;dx++){
                    int xx=tx+dx;
                    v[dy][dx+1] = (xx>=0&&xx<64)? cur[ty+dy][xx] : 0.f;
                }
            float gx = (v[0][2]+2.f*v[1][2]+v[2][2]) - (v[0][0]+2.f*v[1][0]+v[2][0]);
            float gy = (v[2][0]+2.f*v[2][1]+v[2][2]) - (v[0][0]+2.f*v[0][1]+v[0][2]);
            ssum += sqrtf(gx*gx+gy*gy);
            float ctr = v[1][1];
            csum += ctr; mx = fmaxf(mx,ctr); mn = fminf(mn,ctr);
            __syncthreads();
        }
        int id = (b<<12) + (y<<6) + tx;
        g_sobel[id] = sigmoidf_(ssum*(1.0f/64.0f));
        g_hsv[id]   = (mx-mn+1e-6f)/(mx+1e-6f);
        g_hist[id]  = sigmoidf_(csum*(1.0f/64.0f));
    } else {
        // ---- fftA: row DFT (ungated, Hermitian v=0..32), 32 rows per block
        float* xs = (float*)sm8;   // [32][65] = 2080 floats
        const int e = blk - 1664;
        const int rh = e&1, c = (e>>1)&63, b = e>>7;
        const int r0 = rh*32;
        const float* xp = x + ((size_t)(((b<<6)+c))<<12) + (r0<<6);
        for (int i=t;i<2048;i+=128){
            int r=i>>6, j=i&63;
            xs[r*65+j] = xp[i];
        }
        __syncthreads();
        const size_t base = (size_t)((b<<6)+c)*NV*64;
        for (int i=t;i<32*NV;i+=128){
            int r = i/NV, v = i - r*NV;
            float st, ct;
            __sincosf(-6.283185307179586f*(float)v*(1.0f/64.0f), &st, &ct);
            float cv=1.f, sv=0.f, cr=0.f, ci=0.f;
            const float* row = xs + r*65;
            #pragma unroll 4
            for (int j=0;j<64;j++){
                float xv = row[j];
                cr += xv*cv; ci += xv*sv;
                float cn = cv*ct - sv*st;
                sv = sv*ct + cv*st;
                cv = cn;
                if ((j&15)==15){   // renormalize phasor to bound drift
                    float nrm = __frsqrt_rn(cv*cv + sv*sv);
                    cv *= nrm; sv *= nrm;
                }
            }
            g_fre[base + v*64 + r0 + r] = cr;
            g_fim[base + v*64 + r0 + r] = ci;
        }
    }
}

// ---------------- fc + argmax ----------------
__global__ void fc_argmax_kernel(const float* __restrict__ fcw,
                                 const float* __restrict__ fcb){
    int wid = threadIdx.x>>5, lane = threadIdx.x&31;
    if (wid >= BB) return;
    float v = -1e30f; int idx = lane;
    if (lane < 25){
        float s = fcb[lane];
        const float* f2   = g_f2 + wid*128;
        const float* wrow = fcw  + lane*128;
        #pragma unroll 4
        for (int k=0;k<128;k++) s += f2[k]*wrow[k];
        v = s;
    }
    #pragma unroll
    for (int off=16;off>0;off>>=1){
        float ov = __shfl_down_sync(0xffffffffu, v,   off);
        int   oi = __shfl_down_sync(0xffffffffu, idx, off);
        if (ov > v || (ov==v && oi<idx)){ v=ov; idx=oi; }
    }
    if (lane==0) g_branch[wid] = c_branch_tab[idx];
}

// ---------------- fftB: col DFT + mag + shift + mirror (gated) ----------------
// grid (128, 4): block = (uhalf, c); outputs u in [uh*32, uh*32+32), v in [0,33)
__global__ void __launch_bounds__(256) fftB_kernel(){
    const int b = blockIdx.y;
    if (g_branch[b] != 3) return;
    __shared__ float Rs[NV*65], Is[NV*65];
    const int e = blockIdx.x;
    const int uh = e&1, c = e>>1;
    const int t = threadIdx.x;
    const size_t base = (size_t)((b<<6)+c)*NV*64;
    for (int i=t;i<NV*64;i+=256){
        int v=i>>6, r=i&63;
        Rs[v*65+r] = g_fre[base+i];
        Is[v*65+r] = g_fim[base+i];
    }
    __syncthreads();
    float* outp = g_fftmag + ((size_t)(((b<<6)+c))<<12);
    for (int i=t;i<32*NV;i+=256){
        int u = uh*32 + i/NV, v = i - (i/NV)*NV;
        float st, ct;
        __sincosf(-6.283185307179586f*(float)u*(1.0f/64.0f), &st, &ct);
        float cu=1.f, su=0.f, fr=0.f, fi=0.f;
        const float* Rp = Rs + v*65;
        const float* Ip = Is + v*65;
        #pragma unroll 4
        for (int r=0;r<64;r++){
            float a=Rp[r], bm=Ip[r];
            fr += a*cu - bm*su;
            fi += a*su + bm*cu;
            float cn = cu*ct - su*st;
            su = su*ct + cu*st;
            cu = cn;
            if ((r&15)==15){   // renormalize phasor to bound drift
                float nrm = __frsqrt_rn(cu*cu + su*su);
                cu *= nrm; su *= nrm;
            }
        }
        float mag = sqrtf(fr*fr+fi*fi);
        int su_=(u+32)&63, sv_=(v+32)&63;
        outp[(su_<<6)+sv_] = mag;
        int u2=(64-u)&63, v2=(64-v)&63;
        int su2=(u2+32)&63, sv2=(v2+32)&63;
        outp[(su2<<6)+sv2] = mag;
    }
}

// ---------------- combine split partials + routed spatial epilogue ----------------
__global__ void __launch_bounds__(256) attn_finish(const float* __restrict__ x,
                                                   const float* __restrict__ swp,
                                                   float* __restrict__ out){
    __shared__ float scl[64];
    const int t = threadIdx.x;
    const int b = blockIdx.y, n0 = blockIdx.x*64;
    if (t < 64){
        float d = 0.f;
        #pragma unroll
        for (int s=0;s<NSPL;s++) d += g_dpart[((s*BB + b)<<12) + n0 + t];
        const int br = g_branch[b];
        const int id = (b<<12) + n0 + t;
        float v;
        if      (br==0) v = g_sobel[id];
        else if (br==1) v = g_hsv[id];
        else if (br==2) v = g_hist[id];
        else {
            float s=0.f;
            const float* mp = g_fftmag + ((size_t)b<<18) + n0 + t;
            #pragma unroll 4
            for (int c=0;c<64;c++) s += mp[(size_t)c<<12];
            v = sigmoidf_(s*(1.0f/64.0f));
        }
        scl[t] = swp[0]*v/d;
    }
    __syncthreads();
    for (int i=t;i<4096;i+=256){
        int c = i>>6, q = i&63;
        size_t po = ((size_t)(b*CC + c)<<12) + n0 + q;
        float osum = 0.f;
        #pragma unroll
        for (int s=0;s<NSPL;s++) osum += g_Opart[((size_t)(s*BB*CC)<<12) + po];
        out[po] = osum*scl[q] + x[po];
    }
}

// ---------------- launch ----------------
extern "C" void kernel_launch(void* const* d_in, const int* in_sizes, int n_in,
                              void* d_out, int out_size){
    const float* x    = (const float*)d_in[0];
    const float* wq   = (const float*)d_in[1];
    const float* bq   = (const float*)d_in[2];
    const float* wk   = (const float*)d_in[3];
    const float* bk   = (const float*)d_in[4];
    const float* wv   = (const float*)d_in[5];
    const float* bv   = (const float*)d_in[6];
    const float* c1w  = (const float*)d_in[7];
    const float* c1b  = (const float*)d_in[8];
    const float* c2w  = (const float*)d_in[9];
    const float* c2b  = (const float*)d_in[10];
    const float* fcw  = (const float*)d_in[11];
    const float* fcb  = (const float*)d_in[12];
    const float* swp  = (const float*)d_in[13];
    float* out = (float*)d_out;

    cudaFuncSetAttribute(phase1_kernel, cudaFuncAttributeMaxDynamicSharedMemorySize, 36864);

    phase1_kernel  <<<512, 256, 36864>>>(x, wq,bq, wk,bk, wv,bv, c1w, c1b);
    phase2_kernel  <<<2176, 128, 19584>>>(x, c2w, c2b);
    fc_argmax_kernel<<<1,128>>>(fcw, fcb);
    fftB_kernel    <<<dim3(128,4), 256>>>();
    attn_finish    <<<dim3(64,4), 256>>>(x, swp, out);
}

// round 8
// speedup vs baseline: 4.8009x; 1.0810x over previous
#include <cuda_runtime.h>
#include <cuda_bf16.h>

#define BB   4
#define CC   64
#define HWD  4096
#define QKD  8
#define NSPL 4
#define NV   33   // Hermitian: v = 0..32

// ---------------- device scratch ----------------
__device__ unsigned       g_Qh[BB*4*HWD];
__device__ unsigned       g_Kh[BB*4*HWD];
__device__ __nv_bfloat16  g_Vh[BB*CC*HWD];
__device__ float g_Opart[NSPL*BB*CC*HWD];
__device__ float g_dpart[NSPL*BB*HWD];
__device__ float g_f1[BB*64*32*32];
__device__ float g_f2[BB*128];
__device__ int   g_branch[BB];
__device__ float g_sobel[BB*HWD];
__device__ float g_hsv[BB*HWD];
__device__ float g_hist[BB*HWD];
__device__ float g_fre[BB*CC*NV*64];   // [b][c][v][r]
__device__ float g_fim[BB*CC*NV*64];
__device__ float g_fftmag[BB*CC*HWD];
__device__ int   g_cnt;    // conv2 completion counter (reset by attn_finish)
__device__ int   g_flag;   // branch-ready flag     (reset by attn_finish)

__device__ const int c_branch_tab[25] =
    {0,0,0,0,0,0,1,1,0,0,0,0,0,0,3,1,1,2,3,0,0,3,3,3,3};

__device__ __forceinline__ float sigmoidf_(float z){ return 1.0f/(1.0f+__expf(-z)); }
__device__ __forceinline__ unsigned pack_bf16x2(float hi, float lo){
    unsigned r; asm("cvt.rn.bf16x2.f32 %0, %1, %2;" : "=r"(r) : "f"(hi), "f"(lo)); return r;
}
__device__ __forceinline__ float ex2_(float v){
    float r; asm("ex2.approx.f32 %0, %1;" : "=f"(r) : "f"(v)); return r;
}

// =====================================================================
// PHASE 1: conv1 (0..255) || qkv (256..511) || fftA row-DFT (512..767).
// 256 thr. dyn smem 36864 B.
// =====================================================================
__global__ void __launch_bounds__(256) phase1_kernel(const float* __restrict__ x,
    const float* __restrict__ wq, const float* __restrict__ bq,
    const float* __restrict__ wk, const float* __restrict__ bk,
    const float* __restrict__ wv, const float* __restrict__ bv,
    const float* __restrict__ c1w, const float* __restrict__ c1b){
    extern __shared__ float smf[];
    const int blk = blockIdx.x, t = threadIdx.x;

    if (blk < 256){
        // ---- conv1: (b, ocg of 2 oc, y-half) -> relu -> g_f1[4,64,32,32]
        const int ocg = blk & 31, yh = (blk>>5)&1, b = blk>>6;
        float* xs = smf;           // 33*64 = 2112
        float* ws = smf + 2112;    // 1152
        for (int i=t;i<1152;i+=256) ws[i] = c1w[ocg*1152 + i];
        float acc[2][2] = {{0.f,0.f},{0.f,0.f}};
        const int px = t&31;
        const int ybase = yh*32 - 1;
        for (int ic=0; ic<64; ++ic){
            __syncthreads();
            const float* xp = x + (((size_t)b*64+ic)<<12);
            for (int i=t;i<2112;i+=256){
                int r=i>>6, xx=i&63, iy=ybase+r;
                xs[i] = (iy>=0 && iy<64) ? xp[(iy<<6)+xx] : 0.f;
            }
            __syncthreads();
            const float* wp0 = ws + ic*9;
            const float* wp1 = ws + 576 + ic*9;
            #pragma unroll
            for (int pi=0;pi<2;pi++){
                int py = (t>>5) + pi*8;
                int r0 = py*2, ix0 = px*2 - 1;
                float v[9];
                #pragma unroll
                for (int ky=0;ky<3;ky++)
                    #pragma unroll
                    for (int kx=0;kx<3;kx++){
                        int ix = ix0+kx;
                        v[ky*3+kx] = (ix>=0&&ix<64)? xs[(r0+ky)*64 + ix] : 0.f;
                    }
                float s0=0.f, s1=0.f;
                #pragma unroll
                for (int k=0;k<9;k++){ s0 += v[k]*wp0[k]; s1 += v[k]*wp1[k]; }
                acc[pi][0]+=s0; acc[pi][1]+=s1;
            }
        }
        #pragma unroll
        for (int ol=0;ol<2;ol++){
            int oc = ocg*2+ol;
            float bvl = c1b[oc];
            #pragma unroll
            for (int pi=0;pi<2;pi++){
                int oy = yh*16 + (t>>5) + pi*8;
                float v = acc[pi][ol]+bvl;
                g_f1[(((b*64)+oc)<<10) + (oy<<5) + px] = v>0.f? v : 0.f;
            }
        }
    } else if (blk < 512){
        // ---- qkv: 64-n tiles, 4 thread-quarters
        const int e = blk - 256;
        const int ntile = e & 63, b = e>>6;
        const int n0 = ntile*64;
        float* wqt = smf;            // 512
        float* wkt = smf + 512;      // 512
        float* wvt = smf + 1024;     // 4096
        float* xs  = smf + 5120;     // 4096 : [c][64]
        for (int i=t;i<512;i+=256){ int o=i>>6,c=i&63; wqt[c*8+o]=wq[i]; wkt[c*8+o]=wk[i]; }
        for (int i=t;i<4096;i+=256){ int o=i>>6,c=i&63; wvt[c*64+o]=wv[i]; }
        {
            const float* xb = x + (size_t)b*CC*HWD + n0;
            for (int i=t;i<4096;i+=256){ int c=i>>6, nl=i&63; xs[i] = xb[(size_t)c*HWD + nl]; }
        }
        __syncthreads();
        const int qt = t>>6, nl = t&63;
        const int n = n0 + nl;
        float av[16], aqk[8];
        #pragma unroll
        for (int o=0;o<16;o++) av[o]=bv[qt*16+o];
        const float* bqk = (qt==1)? bk : bq;
        #pragma unroll
        for (int o=0;o<8;o++) aqk[o]=bqk[o];
        const float* wqkt = (qt==1)? wkt : wqt;
        for (int c=0;c<64;c++){
            float xc = xs[(c<<6) + nl];
            const float4* wv4 = (const float4*)(wvt + c*64 + qt*16);
            #pragma unroll
            for (int j=0;j<4;j++){
                float4 v = wv4[j];
                av[4*j+0]+=v.x*xc; av[4*j+1]+=v.y*xc; av[4*j+2]+=v.z*xc; av[4*j+3]+=v.w*xc;
            }
            if (qt < 2){
                const float4* wq4 = (const float4*)(wqkt + c*8);
                #pragma unroll
                for (int j=0;j<2;j++){
                    float4 q4=wq4[j];
                    aqk[4*j+0]+=q4.x*xc; aqk[4*j+1]+=q4.y*xc; aqk[4*j+2]+=q4.z*xc; aqk[4*j+3]+=q4.w*xc;
                }
            }
        }
        #pragma unroll
        for (int o=0;o<16;o++)
            g_Vh[((size_t)((b<<6)+qt*16+o))*HWD + n] = __float2bfloat16(av[o]);
        if (qt < 2){
            const float f = (qt==1)? 1.0f : (0.35355339059327373f * 1.4426950408889634f);
            unsigned* dst = (qt==1)? g_Kh : g_Qh;
            #pragma unroll
            for (int dp=0;dp<4;dp++)
                dst[((b<<2)+dp)*HWD + n] = pack_bf16x2(aqk[2*dp+1]*f, aqk[2*dp]*f);
        }
    } else {
        // ---- fftA: row DFT (ungated, Hermitian v=0..32), one (b,c) per block
        float* xs = smf;   // [64][65] = 4160 floats = 16640 B
        const int e = blk - 512;
        const int c = e&63, b = e>>6;
        const float* xp = x + ((size_t)(((b<<6)+c))<<12);
        for (int i=t;i<4096;i+=256){
            int r=i>>6, j=i&63;
            xs[r*65+j] = xp[i];
        }
        __syncthreads();
        const size_t base = (size_t)((b<<6)+c)*NV*64;
        for (int i=t;i<64*NV;i+=256){
            int r = i/NV, v = i - r*NV;
            float st, ct;
            __sincosf(-6.283185307179586f*(float)v*(1.0f/64.0f), &st, &ct);
            float cv=1.f, sv=0.f, cr=0.f, ci=0.f;
            const float* row = xs + r*65;
            #pragma unroll 4
            for (int j=0;j<64;j++){
                float xv = row[j];
                cr += xv*cv; ci += xv*sv;
                float cn = cv*ct - sv*st;
                sv = sv*ct + cv*st;
                cv = cn;
                if ((j&15)==15){
                    float nrm = __frsqrt_rn(cv*cv + sv*sv);
                    cv *= nrm; sv *= nrm;
                }
            }
            g_fre[base + v*64 + r] = cr;
            g_fim[base + v*64 + r] = ci;
        }
    }
}

// =====================================================================
// PHASE 2: conv2+fc (0..511, fc by last conv2 block) || attention
// (512..1535) || spatial3 (1536..1663) || fftB gated on flag
// (1664..2175). 128 thr, 19584 B.
// =====================================================================
__global__ void __launch_bounds__(128) phase2_kernel(const float* __restrict__ x,
    const float* __restrict__ c2w, const float* __restrict__ c2b,
    const float* __restrict__ fcw, const float* __restrict__ fcb){
    extern __shared__ char sm8[];
    const int blk = blockIdx.x, t = threadIdx.x;

    if (blk < 512){
        // ---- conv2 + relu + spatial mean -> g_f2[4,128]; last block does fc
        float* smf = (float*)sm8;
        float* xs  = smf;          // 1024
        float* ws  = smf + 1024;   // 576
        float* red = smf + 1600;   // 128
        const int oc = blk & 127, b = blk>>7;
        for (int i=t;i<576;i+=128) ws[i]=c2w[oc*576+i];
        float acc0=0.f, acc1=0.f;
        const int ox = t&15;
        for (int ic=0;ic<64;++ic){
            __syncthreads();
            const float* xp = g_f1 + (((b*64)+ic)<<10);
            for (int i=t;i<1024;i+=128) xs[i]=xp[i];
            __syncthreads();
            const float* wp = ws + ic*9;
            #pragma unroll
            for (int pi=0;pi<2;pi++){
                int oy = (t>>4) + pi*8;
                int iy0=2*oy-1, ix0=2*ox-1;
                float a=0.f;
                #pragma unroll
                for (int ky=0;ky<3;ky++)
                    #pragma unroll
                    for (int kx=0;kx<3;kx++){
                        int iy=iy0+ky, ix=ix0+kx;
                        float xv = (iy>=0&&iy<32&&ix>=0&&ix<32)? xs[(iy<<5)+ix] : 0.0f;
                        a += xv*wp[ky*3+kx];
                    }
                if (pi==0) acc0+=a; else acc1+=a;
            }
        }
        float bvl = c2b[oc];
        float r0 = acc0+bvl; r0 = r0>0.f? r0:0.f;
        float r1 = acc1+bvl; r1 = r1>0.f? r1:0.f;
        red[t]=r0+r1; __syncthreads();
        for (int s=64;s>0;s>>=1){ if(t<s) red[t]+=red[t+s]; __syncthreads(); }
        __shared__ int amlast;
        if (t==0){
            g_f2[b*128+oc] = red[0]*(1.0f/256.0f);
            __threadfence();
            int old = atomicAdd(&g_cnt, 1);
            amlast = (old == 511);
        }
        __syncthreads();
        if (amlast){
            // this block observes all 512 g_f2 writes complete -> fc + argmax
            int wid = t>>5, lane = t&31;
            if (wid < BB){
                float v = -1e30f; int idx = lane;
                if (lane < 25){
                    float s = fcb[lane];
                    const float* f2   = g_f2 + wid*128;
                    const float* wrow = fcw  + lane*128;
                    #pragma unroll 4
                    for (int k=0;k<128;k++) s += f2[k]*wrow[k];
                    v = s;
                }
                #pragma unroll
                for (int off=16;off>0;off>>=1){
                    float ov = __shfl_down_sync(0xffffffffu, v,   off);
                    int   oi = __shfl_down_sync(0xffffffffu, idx, off);
                    if (ov > v || (ov==v && oi<idx)){ v=ov; idx=oi; }
                }
                if (lane==0) g_branch[wid] = c_branch_tab[idx];
            }
            __syncthreads();
            if (t==0){ __threadfence(); atomicExch(&g_flag, 1); }
        }
    } else if (blk < 1536){
        // ---- tensor-core flash attention, split-KV x4
        unsigned* Ksu = (unsigned*)sm8;               // 4*136 u32
        unsigned* Vsu = (unsigned*)(sm8 + 2176);      // 64*68 u32
        float*    Osm = (float*)(sm8 + 2176);
        const int e = blk - 512;
        const int lane = t&31, w = t>>5;
        const int g = lane>>2, l = lane&3;
        const int qt = e & 63, spl = (e>>6)&3, b = e>>8;
        const int n0 = qt*64;
        const int qw = w*16;

        unsigned qa0 = g_Qh[((b<<2)+l)*HWD + n0 + qw + g];
        unsigned qa1 = g_Qh[((b<<2)+l)*HWD + n0 + qw + g + 8];
        const unsigned zz = 0u;

        float o[32];
        #pragma unroll
        for (int i=0;i<32;i++) o[i]=0.f;
        float d0=0.f, d1=0.f;

        const int kt0 = spl*(32/NSPL), kt1 = kt0 + (32/NSPL);
        for (int kt=kt0;kt<kt1;kt++){
            const int m0 = kt<<7;
            __syncthreads();
            {
                int dp = t>>5, j = t&31;
                ((uint4*)(Ksu + dp*136))[j] =
                    ((const uint4*)(g_Kh + ((b<<2)+dp)*HWD + m0))[j];
            }
            for (int i=t;i<1024;i+=128){
                int r = i>>4, j = i&15;
                ((uint4*)(Vsu + r*68))[j] =
                    ((const uint4*)(g_Vh + ((size_t)((b<<6)+r))*HWD + m0))[j];
            }
            __syncthreads();

            #pragma unroll 2
            for (int mc=0;mc<8;mc++){
                const int m16 = mc<<4;
                float s0,s1,s2,s3,s4,s5,s6,s7;
                unsigned kb0 = Ksu[l*136 + m16 + g];
                unsigned kb1 = Ksu[l*136 + m16 + 8 + g];
                asm("mma.sync.aligned.m16n8k16.row.col.f32.bf16.bf16.f32 "
                    "{%0,%1,%2,%3},{%4,%5,%6,%7},{%8,%9},{%10,%11,%12,%13};"
                    : "=f"(s0),"=f"(s1),"=f"(s2),"=f"(s3)
                    : "r"(qa0),"r"(qa1),"r"(zz),"r"(zz), "r"(kb0),"r"(zz),
                      "f"(0.f),"f"(0.f),"f"(0.f),"f"(0.f));
                asm("mma.sync.aligned.m16n8k16.row.col.f32.bf16.bf16.f32 "
                    "{%0,%1,%2,%3},{%4,%5,%6,%7},{%8,%9},{%10,%11,%12,%13};"
                    : "=f"(s4),"=f"(s5),"=f"(s6),"=f"(s7)
                    : "r"(qa0),"r"(qa1),"r"(zz),"r"(zz), "r"(kb1),"r"(zz),
                      "f"(0.f),"f"(0.f),"f"(0.f),"f"(0.f));
                s0=ex2_(s0); s1=ex2_(s1); s2=ex2_(s2); s3=ex2_(s3);
                s4=ex2_(s4); s5=ex2_(s5); s6=ex2_(s6); s7=ex2_(s7);
                d0 += (s0+s1)+(s4+s5);
                d1 += (s2+s3)+(s6+s7);
                unsigned p0 = pack_bf16x2(s1,s0);
                unsigned p1 = pack_bf16x2(s3,s2);
                unsigned p2 = pack_bf16x2(s5,s4);
                unsigned p3 = pack_bf16x2(s7,s6);
                const int vbase = (m16>>1) + l;
                #pragma unroll
                for (int ct=0;ct<8;ct++){
                    unsigned vb0 = Vsu[(ct*8+g)*68 + vbase];
                    unsigned vb1 = Vsu[(ct*8+g)*68 + vbase + 4];
                    asm("mma.sync.aligned.m16n8k16.row.col.f32.bf16.bf16.f32 "
                        "{%0,%1,%2,%3},{%4,%5,%6,%7},{%8,%9},{%0,%1,%2,%3};"
                        : "+f"(o[ct*4+0]),"+f"(o[ct*4+1]),"+f"(o[ct*4+2]),"+f"(o[ct*4+3])
                        : "r"(p0),"r"(p1),"r"(p2),"r"(p3), "r"(vb0),"r"(vb1));
                }
            }
        }
        d0 += __shfl_xor_sync(0xffffffffu, d0, 1);
        d0 += __shfl_xor_sync(0xffffffffu, d0, 2);
        d1 += __shfl_xor_sync(0xffffffffu, d1, 1);
        d1 += __shfl_xor_sync(0xffffffffu, d1, 2);
        if (l == 0){
            g_dpart[((spl*BB + b)<<12) + n0 + qw + g    ] = d0;
            g_dpart[((spl*BB + b)<<12) + n0 + qw + g + 8] = d1;
        }

        __syncthreads();
        #pragma unroll
        for (int ct=0;ct<8;ct++){
            int c0 = ct*8 + 2*l;
            Osm[ c0   *68 + qw + g    ] = o[ct*4+0];
            Osm[(c0+1)*68 + qw + g    ] = o[ct*4+1];
            Osm[ c0   *68 + qw + g + 8] = o[ct*4+2];
            Osm[(c0+1)*68 + qw + g + 8] = o[ct*4+3];
        }
        __syncthreads();
        float* op = g_Opart + ((size_t)(spl*BB + b)*CC<<12) + n0;
        for (int i=t;i<4096;i+=128){
            int c = i>>6, q = i&63;
            op[((size_t)c<<12) + q] = Osm[c*68+q];
        }
    } else if (blk < 1664){
        // ---- sobel/hsv/hist maps (ungated), 2 rows per block
        float (*xs)[4][64] = (float (*)[4][64])sm8;
        const int e = blk - 1536;
        const int seg = e & 31, b = e>>5;
        const int y0 = seg*2;
        const int ty = t>>6, tx = t&63;
        const int y = y0 + ty;
        const float* xb = x + ((size_t)b<<18);
        float ssum=0.f, csum=0.f, mx=-1e30f, mn=1e30f;
        #pragma unroll
        for (int i=t;i<256;i+=128){
            int r=i>>6, xx=i&63, yy=y0-1+r;
            xs[0][r][xx] = (yy>=0&&yy<64)? xb[(yy<<6)+xx] : 0.f;
        }
        __syncthreads();
        for (int c=0;c<64;c++){
            if (c+1<64){
                const float* xp = xb + ((size_t)(c+1)<<12);
                #pragma unroll
                for (int i=t;i<256;i+=128){
                    int r=i>>6, xx=i&63, yy=y0-1+r;
                    xs[(c+1)&1][r][xx] = (yy>=0&&yy<64)? xp[(yy<<6)+xx] : 0.f;
                }
            }
            const float (*cur)[64] = xs[c&1];
            float v[3][3];
            #pragma unroll
            for (int dy=0;dy<3;dy++)
                #pragma unroll
                for (int dx=-1;dx<=1;dx++){
                    int xx=tx+dx;
                    v[dy][dx+1] = (xx>=0&&xx<64)? cur[ty+dy][xx] : 0.f;
                }
            float gx = (v[0][2]+2.f*v[1][2]+v[2][2]) - (v[0][0]+2.f*v[1][0]+v[2][0]);
            float gy = (v[2][0]+2.f*v[2][1]+v[2][2]) - (v[0][0]+2.f*v[0][1]+v[0][2]);
            ssum += sqrtf(gx*gx+gy*gy);
            float ctr = v[1][1];
            csum += ctr; mx = fmaxf(mx,ctr); mn = fminf(mn,ctr);
            __syncthreads();
        }
        int id = (b<<12) + (y<<6) + tx;
        g_sobel[id] = sigmoidf_(ssum*(1.0f/64.0f));
        g_hsv[id]   = (mx-mn+1e-6f)/(mx+1e-6f);
        g_hist[id]  = sigmoidf_(csum*(1.0f/64.0f));
    } else {
        // ---- fftB: wait for branch flag, then col DFT + mag (gated)
        const int e = blk - 1664;
        const int uh = e&1, c = (e>>1)&63, b = e>>7;
        if (t==0){
            while (atomicAdd(&g_flag, 0) == 0) __nanosleep(200);
        }
        __syncthreads();
        __threadfence();
        volatile int* vbr = g_branch;
        if (vbr[b] != 3) return;
        float* Rs = (float*)sm8;            // NV*65
        float* Is = Rs + NV*65;
        const size_t base = (size_t)((b<<6)+c)*NV*64;
        for (int i=t;i<NV*64;i+=128){
            int v=i>>6, r=i&63;
            Rs[v*65+r] = g_fre[base+i];
            Is[v*65+r] = g_fim[base+i];
        }
        __syncthreads();
        float* outp = g_fftmag + ((size_t)(((b<<6)+c))<<12);
        for (int i=t;i<32*NV;i+=128){
            int u = uh*32 + i/NV, v = i - (i/NV)*NV;
            float st, ct;
            __sincosf(-6.283185307179586f*(float)u*(1.0f/64.0f), &st, &ct);
            float cu=1.f, su=0.f, fr=0.f, fi=0.f;
            const float* Rp = Rs + v*65;
            const float* Ip = Is + v*65;
            #pragma unroll 4
            for (int r=0;r<64;r++){
                float a=Rp[r], bm=Ip[r];
                fr += a*cu - bm*su;
                fi += a*su + bm*cu;
                float cn = cu*ct - su*st;
                su = su*ct + cu*st;
                cu = cn;
                if ((r&15)==15){
                    float nrm = __frsqrt_rn(cu*cu + su*su);
                    cu *= nrm; su *= nrm;
                }
            }
            float mag = sqrtf(fr*fr+fi*fi);
            int su_=(u+32)&63, sv_=(v+32)&63;
            outp[(su_<<6)+sv_] = mag;
            int u2=(64-u)&63, v2=(64-v)&63;
            int su2=(u2+32)&63, sv2=(v2+32)&63;
            outp[(su2<<6)+sv2] = mag;
        }
    }
}

// ---------------- combine split partials + routed spatial epilogue ----------------
__global__ void __launch_bounds__(256) attn_finish(const float* __restrict__ x,
                                                   const float* __restrict__ swp,
                                                   float* __restrict__ out){
    __shared__ float scl[64];
    const int t = threadIdx.x;
    const int b = blockIdx.y, n0 = blockIdx.x*64;
    if (blockIdx.x==0 && blockIdx.y==0 && t==0){ g_cnt = 0; g_flag = 0; }  // reset for next replay
    if (t < 64){
        float d = 0.f;
        #pragma unroll
        for (int s=0;s<NSPL;s++) d += g_dpart[((s*BB + b)<<12) + n0 + t];
        const int br = g_branch[b];
        const int id = (b<<12) + n0 + t;
        float v;
        if      (br==0) v = g_sobel[id];
        else if (br==1) v = g_hsv[id];
        else if (br==2) v = g_hist[id];
        else {
            float s=0.f;
            const float* mp = g_fftmag + ((size_t)b<<18) + n0 + t;
            #pragma unroll 4
            for (int c=0;c<64;c++) s += mp[(size_t)c<<12];
            v = sigmoidf_(s*(1.0f/64.0f));
        }
        scl[t] = swp[0]*v/d;
    }
    __syncthreads();
    for (int i=t;i<4096;i+=256){
        int c = i>>6, q = i&63;
        size_t po = ((size_t)(b*CC + c)<<12) + n0 + q;
        float osum = 0.f;
        #pragma unroll
        for (int s=0;s<NSPL;s++) osum += g_Opart[((size_t)(s*BB*CC)<<12) + po];
        out[po] = osum*scl[q] + x[po];
    }
}

// ---------------- launch ----------------
extern "C" void kernel_launch(void* const* d_in, const int* in_sizes, int n_in,
                              void* d_out, int out_size){
    const float* x    = (const float*)d_in[0];
    const float* wq   = (const float*)d_in[1];
    const float* bq   = (const float*)d_in[2];
    const float* wk   = (const float*)d_in[3];
    const float* bk   = (const float*)d_in[4];
    const float* wv   = (const float*)d_in[5];
    const float* bv   = (const float*)d_in[6];
    const float* c1w  = (const float*)d_in[7];
    const float* c1b  = (const float*)d_in[8];
    const float* c2w  = (const float*)d_in[9];
    const float* c2b  = (const float*)d_in[10];
    const float* fcw  = (const float*)d_in[11];
    const float* fcb  = (const float*)d_in[12];
    const float* swp  = (const float*)d_in[13];
    float* out = (float*)d_out;

    cudaFuncSetAttribute(phase1_kernel, cudaFuncAttributeMaxDynamicSharedMemorySize, 36864);

    phase1_kernel  <<<768, 256, 36864>>>(x, wq,bq, wk,bk, wv,bv, c1w, c1b);
    phase2_kernel  <<<2176, 128, 19584>>>(x, c2w, c2b, fcw, fcb);
    attn_finish    <<<dim3(64,4), 256>>>(x, swp, out);
}